// round 1
// baseline (speedup 1.0000x reference)
#include <cuda_runtime.h>
#include <math.h>

#define B_   256
#define T_   256
#define C_   512
#define H_   64
#define BT_  (B_ * T_)

// scratch for projected q, k, v  (each 16 MB fp32)
__device__ float g_q[BT_ * H_];
__device__ float g_k[BT_ * H_];
__device__ float g_v[BT_ * H_];

// ---------------------------------------------------------------------------
// Kernel 1: QKV projection.  out[bt, h] = sum_c x[bt, c] * W[c, h]
// Tile: 128 rows x 64 cols per block, kc-step 32. 256 threads, 8x4 per thread.
// gridDim.x = BT/128, gridDim.y = 3 (q, k, v)
// ---------------------------------------------------------------------------
__global__ __launch_bounds__(256) void qkv_gemm(
    const float* __restrict__ x,
    const float* __restrict__ Wq,
    const float* __restrict__ Wk,
    const float* __restrict__ Wv)
{
    __shared__ float xs[128][32];
    __shared__ float ws[32][64];

    const int tid = threadIdx.x;
    const int tx  = tid & 15;   // col group: 4 cols
    const int ty  = tid >> 4;   // row group: 8 rows
    const int row0 = blockIdx.x * 128;

    const float* W;
    float* out;
    if (blockIdx.y == 0)      { W = Wq; out = g_q; }
    else if (blockIdx.y == 1) { W = Wk; out = g_k; }
    else                      { W = Wv; out = g_v; }

    float acc[8][4];
#pragma unroll
    for (int i = 0; i < 8; i++)
#pragma unroll
        for (int j = 0; j < 4; j++) acc[i][j] = 0.f;

    for (int kc = 0; kc < C_; kc += 32) {
        // load x tile [128][32]
#pragma unroll
        for (int i = tid; i < 128 * 32; i += 256) {
            int r = i >> 5, k = i & 31;
            xs[r][k] = x[(size_t)(row0 + r) * C_ + kc + k];
        }
        // load W tile [32][64]
#pragma unroll
        for (int i = tid; i < 32 * 64; i += 256) {
            int r = i >> 6, c = i & 63;
            ws[r][c] = W[(kc + r) * H_ + c];
        }
        __syncthreads();

#pragma unroll
        for (int k = 0; k < 32; k++) {
            float4 b = *(const float4*)&ws[k][tx * 4];
#pragma unroll
            for (int i = 0; i < 8; i++) {
                float a = xs[ty * 8 + i][k];
                acc[i][0] += a * b.x;
                acc[i][1] += a * b.y;
                acc[i][2] += a * b.z;
                acc[i][3] += a * b.w;
            }
        }
        __syncthreads();
    }

#pragma unroll
    for (int i = 0; i < 8; i++) {
        float4 v = make_float4(acc[i][0], acc[i][1], acc[i][2], acc[i][3]);
        *(float4*)&out[(size_t)(row0 + ty * 8 + i) * H_ + tx * 4] = v;
    }
}

// ---------------------------------------------------------------------------
// Kernel 2: causal flash attention over one (batch, 64-query tile).
// 64 threads: one query row per thread. q, o in registers (float4[16]).
// k/v tiles (64 keys x 64) staged in smem, scores in smem ss[s][tid].
// grid = (B, T/64)
// ---------------------------------------------------------------------------
__global__ __launch_bounds__(64) void attn_kernel(float* __restrict__ out)
{
    __shared__ float ks[64 * 64];   // ks[s*64 + h]
    __shared__ float vs[64 * 64];   // vs[s*64 + h]
    __shared__ float ss[64 * 64];   // ss[s*64 + tid]  (per-thread score column)

    const int b   = blockIdx.x;
    const int qt  = blockIdx.y;
    const int tid = threadIdx.x;          // 0..63
    const int qi  = qt * 64 + tid;        // global query index
    const float SCALE = 0.04419417382415922f;  // 512^-0.5

    // load this thread's q row into registers
    float4 q4[16];
    {
        const float4* qp = (const float4*)(g_q + ((size_t)b * T_ + qi) * H_);
#pragma unroll
        for (int i = 0; i < 16; i++) q4[i] = qp[i];
    }

    float4 o4[16];
#pragma unroll
    for (int i = 0; i < 16; i++) o4[i] = make_float4(0.f, 0.f, 0.f, 0.f);
    float m = -INFINITY;
    float l = 0.f;

    const int t4 = tid & 15;   // float4 col for cooperative loads
    const int r0 = tid >> 4;   // row group (4 rows per pass)

    for (int kt = 0; kt <= qt; kt++) {
        // cooperative load of k tile and v tile (coalesced float4)
        const float4* kg = (const float4*)(g_k + ((size_t)b * T_ + kt * 64) * H_);
        const float4* vg = (const float4*)(g_v + ((size_t)b * T_ + kt * 64) * H_);
        float4* ks4 = (float4*)ks;
        float4* vs4 = (float4*)vs;
#pragma unroll
        for (int s = r0; s < 64; s += 4) {
            ks4[s * 16 + t4] = kg[s * 16 + t4];
            vs4[s * 16 + t4] = vg[s * 16 + t4];
        }
        __syncthreads();

        const int smax = (kt == qt) ? (tid + 1) : 64;   // exact causal bound

        // Pass A: scores for this tile -> ss, track tile max
        float mt = -INFINITY;
        for (int s = 0; s < smax; s++) {
            const float4* kr = (const float4*)(ks + s * 64);
            float d0 = 0.f, d1 = 0.f, d2 = 0.f, d3 = 0.f;
#pragma unroll
            for (int i = 0; i < 16; i++) {
                float4 kk = kr[i];
                d0 += q4[i].x * kk.x;
                d1 += q4[i].y * kk.y;
                d2 += q4[i].z * kk.z;
                d3 += q4[i].w * kk.w;
            }
            float d = ((d0 + d1) + (d2 + d3)) * SCALE;
            ss[s * 64 + tid] = d;
            mt = fmaxf(mt, d);
        }

        // online softmax rescale
        float mnew = fmaxf(m, mt);
        float corr = __expf(m - mnew);    // 0 on first tile (m = -inf)
        l *= corr;
#pragma unroll
        for (int i = 0; i < 16; i++) {
            o4[i].x *= corr; o4[i].y *= corr; o4[i].z *= corr; o4[i].w *= corr;
        }
        m = mnew;

        // Pass B: p = exp(s - m); o += p * v
        for (int s = 0; s < smax; s++) {
            float p = __expf(ss[s * 64 + tid] - m);
            l += p;
            const float4* vr = (const float4*)(vs + s * 64);
#pragma unroll
            for (int i = 0; i < 16; i++) {
                float4 vv = vr[i];
                o4[i].x += p * vv.x;
                o4[i].y += p * vv.y;
                o4[i].z += p * vv.z;
                o4[i].w += p * vv.w;
            }
        }
        __syncthreads();   // before next tile overwrites ks/vs
    }

    // finalize and write
    float inv = 1.f / l;
    float4* op = (float4*)(out + ((size_t)b * T_ + qi) * H_);
#pragma unroll
    for (int i = 0; i < 16; i++) {
        float4 v = o4[i];
        v.x *= inv; v.y *= inv; v.z *= inv; v.w *= inv;
        op[i] = v;
    }
}

// ---------------------------------------------------------------------------
extern "C" void kernel_launch(void* const* d_in, const int* in_sizes, int n_in,
                              void* d_out, int out_size)
{
    const float* x  = (const float*)d_in[0];
    const float* Wk = (const float*)d_in[1];
    const float* Wq = (const float*)d_in[2];
    const float* Wv = (const float*)d_in[3];
    float* out = (float*)d_out;

    dim3 g1(BT_ / 128, 3);
    qkv_gemm<<<g1, 256>>>(x, Wq, Wk, Wv);

    dim3 g2(B_, T_ / 64);
    attn_kernel<<<g2, 64>>>(out);
}

// round 4
// speedup vs baseline: 1.3949x; 1.3949x over previous
#include <cuda_runtime.h>
#include <cuda_bf16.h>
#include <math.h>
#include <stdint.h>

#define B_   256
#define T_   256
#define C_   512
#define H_   64
#define BT_  (B_ * T_)

// scratch for projected q, k, v  (each 16 MB fp32)
__device__ float g_q[BT_ * H_];
__device__ float g_k[BT_ * H_];
__device__ float g_v[BT_ * H_];

// ---------------------------------------------------------------------------
// helpers
// ---------------------------------------------------------------------------
__device__ __forceinline__ uint32_t smem_u32(const void* p) {
    uint32_t a;
    asm("{ .reg .u64 t; cvta.to.shared.u64 t, %1; cvt.u32.u64 %0, t; }"
        : "=r"(a) : "l"(p));
    return a;
}

__device__ __forceinline__ void ldsm_x4(uint32_t& r0, uint32_t& r1,
                                        uint32_t& r2, uint32_t& r3,
                                        uint32_t addr) {
    asm volatile("ldmatrix.sync.aligned.m8n8.x4.shared.b16 {%0,%1,%2,%3}, [%4];"
                 : "=r"(r0), "=r"(r1), "=r"(r2), "=r"(r3) : "r"(addr));
}

__device__ __forceinline__ void mma_bf16(float* c, const uint32_t* a,
                                         const uint32_t* b) {
    asm volatile(
        "mma.sync.aligned.m16n8k16.row.col.f32.bf16.bf16.f32 "
        "{%0,%1,%2,%3}, {%4,%5,%6,%7}, {%8,%9}, {%0,%1,%2,%3};"
        : "+f"(c[0]), "+f"(c[1]), "+f"(c[2]), "+f"(c[3])
        : "r"(a[0]), "r"(a[1]), "r"(a[2]), "r"(a[3]),
          "r"(b[0]), "r"(b[1]));
}

// ---------------------------------------------------------------------------
// Kernel 1: QKV projection via mma.sync bf16 with hi/lo split (3 terms).
// grid = (3, BT/128). CTA: 128 rows x 64 cols, 256 threads (8 warps, 4Mx2N),
// warp tile 32x32. K in 8 chunks of 64.
//
// smem (dynamic, bytes), bf16 tiles with row stride 72 halves (144 B):
//   A_hi [128][64] @ 0       (18432)
//   A_lo [128][64] @ 18432   (18432)
//   B_hi [ 64][64] @ 36864   ( 9216)   B[n][k] = W[k][n]
//   B_lo [ 64][64] @ 46080   ( 9216)
// ---------------------------------------------------------------------------
#define QK_AH 0
#define QK_AL 18432
#define QK_BH 36864
#define QK_BL 46080
#define QK_SMEM 55296
#define RS 72   // row stride in halves (144 bytes)

__global__ __launch_bounds__(256) void qkv_gemm_mma(
    const float* __restrict__ x,
    const float* __restrict__ Wq,
    const float* __restrict__ Wk,
    const float* __restrict__ Wv)
{
    extern __shared__ char sm[];
    const uint32_t smb = smem_u32(sm);

    const int tid  = threadIdx.x;
    const int wid  = tid >> 5;
    const int lane = tid & 31;
    const int row0 = blockIdx.y * 128;

    const float* W;
    float* out;
    if (blockIdx.x == 0)      { W = Wq; out = g_q; }
    else if (blockIdx.x == 1) { W = Wk; out = g_k; }
    else                      { W = Wv; out = g_v; }

    const int wm = wid & 3;          // warp M index (0..3)
    const int wn = wid >> 2;         // warp N index (0..1)
    const int m0 = wm * 32;          // warp tile origin within CTA tile
    const int n0 = wn * 32;

    float c[2][4][4];
#pragma unroll
    for (int mt = 0; mt < 2; mt++)
#pragma unroll
        for (int nt = 0; nt < 4; nt++)
#pragma unroll
            for (int i = 0; i < 4; i++) c[mt][nt][i] = 0.f;

    // precomputed ldmatrix lane addresses (byte offsets within tiles)
    // A: row = m0 + mt*16 + (lane&15); col halves = ks*16 + (lane>>4)*8
    const uint32_t a_row_off = (uint32_t)(m0 + (lane & 15)) * (RS * 2)
                             + (uint32_t)(lane >> 4) * 16;
    // B: n = n0 + np*16 + ((lane>>4)&1)*8 + (lane&7); koff = ks*16 + ((lane>>3)&1)*8
    const uint32_t b_row_off = (uint32_t)(n0 + ((lane >> 4) & 1) * 8 + (lane & 7)) * (RS * 2)
                             + (uint32_t)((lane >> 3) & 1) * 16;

    const float4* x4 = (const float4*)x;

    for (int ch = 0; ch < 8; ch++) {
        const int c0 = ch * 64;

        // ---- x tile [128][64] fp32 -> bf16 hi/lo ----
#pragma unroll
        for (int it = 0; it < 8; it++) {
            int idx = tid + it * 256;          // 0..2047 float4s
            int r  = idx >> 4;
            int c4 = idx & 15;
            float4 v = x4[(size_t)(row0 + r) * 128 + (c0 >> 2) + c4];

            __nv_bfloat16 h0 = __float2bfloat16(v.x);
            __nv_bfloat16 h1 = __float2bfloat16(v.y);
            __nv_bfloat16 h2 = __float2bfloat16(v.z);
            __nv_bfloat16 h3 = __float2bfloat16(v.w);
            __nv_bfloat16 l0 = __float2bfloat16(v.x - __bfloat162float(h0));
            __nv_bfloat16 l1 = __float2bfloat16(v.y - __bfloat162float(h1));
            __nv_bfloat16 l2 = __float2bfloat16(v.z - __bfloat162float(h2));
            __nv_bfloat16 l3 = __float2bfloat16(v.w - __bfloat162float(h3));

            uint32_t hA = ((uint32_t)__bfloat16_as_ushort(h1) << 16) | __bfloat16_as_ushort(h0);
            uint32_t hB = ((uint32_t)__bfloat16_as_ushort(h3) << 16) | __bfloat16_as_ushort(h2);
            uint32_t lA = ((uint32_t)__bfloat16_as_ushort(l1) << 16) | __bfloat16_as_ushort(l0);
            uint32_t lB = ((uint32_t)__bfloat16_as_ushort(l3) << 16) | __bfloat16_as_ushort(l2);

            uint32_t off = (uint32_t)r * (RS * 2) + (uint32_t)c4 * 8;
            *(uint2*)(sm + QK_AH + off) = make_uint2(hA, hB);
            *(uint2*)(sm + QK_AL + off) = make_uint2(lA, lB);
        }

        // ---- W tile: Bs[n][k] = W[c0+k][n], 64x64 ----
#pragma unroll
        for (int it = 0; it < 4; it++) {
            int idx4 = tid + it * 256;         // 0..1023 float4s
            int k  = idx4 >> 4;
            int n4 = idx4 & 15;
            float4 v = *(const float4*)&W[(size_t)(c0 + k) * 64 + n4 * 4];
            float vv[4] = {v.x, v.y, v.z, v.w};
#pragma unroll
            for (int j = 0; j < 4; j++) {
                int n = n4 * 4 + j;
                __nv_bfloat16 h = __float2bfloat16(vv[j]);
                __nv_bfloat16 l = __float2bfloat16(vv[j] - __bfloat162float(h));
                uint32_t off = (uint32_t)n * (RS * 2) + (uint32_t)k * 2;
                *(__nv_bfloat16*)(sm + QK_BH + off) = h;
                *(__nv_bfloat16*)(sm + QK_BL + off) = l;
            }
        }
        __syncthreads();

        // ---- mma over 4 k-steps of 16 ----
#pragma unroll
        for (int ks = 0; ks < 4; ks++) {
            uint32_t a_hi[2][4], a_lo[2][4];
#pragma unroll
            for (int mt = 0; mt < 2; mt++) {
                uint32_t off = a_row_off + (uint32_t)mt * 16 * (RS * 2)
                             + (uint32_t)ks * 32;
                ldsm_x4(a_hi[mt][0], a_hi[mt][1], a_hi[mt][2], a_hi[mt][3],
                        smb + QK_AH + off);
                ldsm_x4(a_lo[mt][0], a_lo[mt][1], a_lo[mt][2], a_lo[mt][3],
                        smb + QK_AL + off);
            }
            uint32_t b_hi[4][2], b_lo[4][2];
#pragma unroll
            for (int np = 0; np < 2; np++) {
                uint32_t off = b_row_off + (uint32_t)np * 16 * (RS * 2)
                             + (uint32_t)ks * 32;
                ldsm_x4(b_hi[np*2][0], b_hi[np*2][1], b_hi[np*2+1][0], b_hi[np*2+1][1],
                        smb + QK_BH + off);
                ldsm_x4(b_lo[np*2][0], b_lo[np*2][1], b_lo[np*2+1][0], b_lo[np*2+1][1],
                        smb + QK_BL + off);
            }
#pragma unroll
            for (int mt = 0; mt < 2; mt++)
#pragma unroll
                for (int nt = 0; nt < 4; nt++) {
                    mma_bf16(c[mt][nt], a_hi[mt], b_hi[nt]);
                    mma_bf16(c[mt][nt], a_hi[mt], b_lo[nt]);
                    mma_bf16(c[mt][nt], a_lo[mt], b_hi[nt]);
                }
        }
        __syncthreads();
    }

    // ---- epilogue ----
    const int g  = lane >> 2;
    const int tg = lane & 3;
#pragma unroll
    for (int mt = 0; mt < 2; mt++)
#pragma unroll
        for (int nt = 0; nt < 4; nt++) {
            int row = row0 + m0 + mt * 16 + g;
            int col = n0 + nt * 8 + tg * 2;
            *(float2*)&out[(size_t)row * 64 + col] =
                make_float2(c[mt][nt][0], c[mt][nt][1]);
            *(float2*)&out[(size_t)(row + 8) * 64 + col] =
                make_float2(c[mt][nt][2], c[mt][nt][3]);
        }
}

// ---------------------------------------------------------------------------
// Kernel 2: causal flash attention (scalar; at scalar-FMA roofline).
// Heavy (large qt) tiles launch first via qt flip.
// ---------------------------------------------------------------------------
__global__ __launch_bounds__(64) void attn_kernel(float* __restrict__ out)
{
    __shared__ float ks[64 * 64];
    __shared__ float vs[64 * 64];
    __shared__ float ss[64 * 64];

    const int b   = blockIdx.x;
    const int qt  = (T_ / 64 - 1) - blockIdx.y;   // heavy tiles first
    const int tid = threadIdx.x;
    const int qi  = qt * 64 + tid;
    const float SCALE = 0.04419417382415922f;     // 512^-0.5

    float4 q4[16];
    {
        const float4* qp = (const float4*)(g_q + ((size_t)b * T_ + qi) * H_);
#pragma unroll
        for (int i = 0; i < 16; i++) q4[i] = qp[i];
    }

    float4 o4[16];
#pragma unroll
    for (int i = 0; i < 16; i++) o4[i] = make_float4(0.f, 0.f, 0.f, 0.f);
    float m = -INFINITY;
    float l = 0.f;

    const int t4 = tid & 15;
    const int r0 = tid >> 4;

    for (int kt = 0; kt <= qt; kt++) {
        const float4* kg = (const float4*)(g_k + ((size_t)b * T_ + kt * 64) * H_);
        const float4* vg = (const float4*)(g_v + ((size_t)b * T_ + kt * 64) * H_);
        float4* ks4 = (float4*)ks;
        float4* vs4 = (float4*)vs;
#pragma unroll
        for (int s = r0; s < 64; s += 4) {
            ks4[s * 16 + t4] = kg[s * 16 + t4];
            vs4[s * 16 + t4] = vg[s * 16 + t4];
        }
        __syncthreads();

        const int smax = (kt == qt) ? (tid + 1) : 64;

        float mt = -INFINITY;
        for (int s = 0; s < smax; s++) {
            const float4* kr = (const float4*)(ks + s * 64);
            float d0 = 0.f, d1 = 0.f, d2 = 0.f, d3 = 0.f;
#pragma unroll
            for (int i = 0; i < 16; i++) {
                float4 kk = kr[i];
                d0 += q4[i].x * kk.x;
                d1 += q4[i].y * kk.y;
                d2 += q4[i].z * kk.z;
                d3 += q4[i].w * kk.w;
            }
            float d = ((d0 + d1) + (d2 + d3)) * SCALE;
            ss[s * 64 + tid] = d;
            mt = fmaxf(mt, d);
        }

        float mnew = fmaxf(m, mt);
        float corr = __expf(m - mnew);
        l *= corr;
#pragma unroll
        for (int i = 0; i < 16; i++) {
            o4[i].x *= corr; o4[i].y *= corr; o4[i].z *= corr; o4[i].w *= corr;
        }
        m = mnew;

        for (int s = 0; s < smax; s++) {
            float p = __expf(ss[s * 64 + tid] - m);
            l += p;
            const float4* vr = (const float4*)(vs + s * 64);
#pragma unroll
            for (int i = 0; i < 16; i++) {
                float4 vv = vr[i];
                o4[i].x += p * vv.x;
                o4[i].y += p * vv.y;
                o4[i].z += p * vv.z;
                o4[i].w += p * vv.w;
            }
        }
        __syncthreads();
    }

    float inv = 1.f / l;
    float4* op = (float4*)(out + ((size_t)b * T_ + qi) * H_);
#pragma unroll
    for (int i = 0; i < 16; i++) {
        float4 v = o4[i];
        v.x *= inv; v.y *= inv; v.z *= inv; v.w *= inv;
        op[i] = v;
    }
}

// ---------------------------------------------------------------------------
extern "C" void kernel_launch(void* const* d_in, const int* in_sizes, int n_in,
                              void* d_out, int out_size)
{
    const float* x  = (const float*)d_in[0];
    const float* Wk = (const float*)d_in[1];
    const float* Wq = (const float*)d_in[2];
    const float* Wv = (const float*)d_in[3];
    float* out = (float*)d_out;

    cudaFuncSetAttribute(qkv_gemm_mma,
                         cudaFuncAttributeMaxDynamicSharedMemorySize, QK_SMEM);

    dim3 g1(3, BT_ / 128);
    qkv_gemm_mma<<<g1, 256, QK_SMEM>>>(x, Wq, Wk, Wv);

    dim3 g2(B_, T_ / 64);
    attn_kernel<<<g2, 64>>>(out);
}

// round 5
// speedup vs baseline: 1.5195x; 1.0893x over previous
#include <cuda_runtime.h>
#include <cuda_bf16.h>
#include <math.h>
#include <stdint.h>

#define B_   256
#define T_   256
#define C_   512
#define H_   64
#define BT_  (B_ * T_)

// projected q (pre-scaled), k, v as bf16 hi/lo pairs (8 MB each)
__device__ __nv_bfloat16 g_qh[BT_ * H_];
__device__ __nv_bfloat16 g_ql[BT_ * H_];
__device__ __nv_bfloat16 g_kh[BT_ * H_];
__device__ __nv_bfloat16 g_kl[BT_ * H_];
__device__ __nv_bfloat16 g_vh[BT_ * H_];
__device__ __nv_bfloat16 g_vl[BT_ * H_];

// W in B-operand layout [w][n=64][k=512], bf16 hi/lo
__device__ __nv_bfloat16 g_wbh[3 * H_ * C_];
__device__ __nv_bfloat16 g_wbl[3 * H_ * C_];

// ---------------------------------------------------------------------------
// helpers
// ---------------------------------------------------------------------------
__device__ __forceinline__ uint32_t smem_u32(const void* p) {
    uint32_t a;
    asm("{ .reg .u64 t; cvta.to.shared.u64 t, %1; cvt.u32.u64 %0, t; }"
        : "=r"(a) : "l"(p));
    return a;
}

__device__ __forceinline__ void ldsm_x4(uint32_t& r0, uint32_t& r1,
                                        uint32_t& r2, uint32_t& r3,
                                        uint32_t addr) {
    asm volatile("ldmatrix.sync.aligned.m8n8.x4.shared.b16 {%0,%1,%2,%3}, [%4];"
                 : "=r"(r0), "=r"(r1), "=r"(r2), "=r"(r3) : "r"(addr));
}

__device__ __forceinline__ void ldsm_x4_t(uint32_t& r0, uint32_t& r1,
                                          uint32_t& r2, uint32_t& r3,
                                          uint32_t addr) {
    asm volatile("ldmatrix.sync.aligned.m8n8.x4.trans.shared.b16 {%0,%1,%2,%3}, [%4];"
                 : "=r"(r0), "=r"(r1), "=r"(r2), "=r"(r3) : "r"(addr));
}

__device__ __forceinline__ void mma_bf16(float* c, const uint32_t* a,
                                         const uint32_t* b) {
    asm volatile(
        "mma.sync.aligned.m16n8k16.row.col.f32.bf16.bf16.f32 "
        "{%0,%1,%2,%3}, {%4,%5,%6,%7}, {%8,%9}, {%0,%1,%2,%3};"
        : "+f"(c[0]), "+f"(c[1]), "+f"(c[2]), "+f"(c[3])
        : "r"(a[0]), "r"(a[1]), "r"(a[2]), "r"(a[3]),
          "r"(b[0]), "r"(b[1]));
}

__device__ __forceinline__ uint32_t pack_bf16x2(float lo, float hi) {
    __nv_bfloat162 t = __floats2bfloat162_rn(lo, hi);
    return *(uint32_t*)&t;
}

#define RS2 144   // smem row stride in bytes (72 halves)

// ---------------------------------------------------------------------------
// Kernel 0: W -> bf16 hi/lo in [w][h][c] layout
// ---------------------------------------------------------------------------
__global__ void wconv(const float* __restrict__ Wq,
                      const float* __restrict__ Wk,
                      const float* __restrict__ Wv)
{
    int idx = blockIdx.x * 256 + threadIdx.x;   // 0 .. 3*64*512-1
    if (idx >= 3 * H_ * C_) return;
    int w = idx / (H_ * C_);
    int r = idx % (H_ * C_);
    int h = r / C_;
    int c = r % C_;
    const float* W = (w == 0) ? Wq : (w == 1) ? Wk : Wv;
    float v = W[(size_t)c * H_ + h];
    __nv_bfloat16 hi = __float2bfloat16(v);
    __nv_bfloat16 lo = __float2bfloat16(v - __bfloat162float(hi));
    g_wbh[idx] = hi;
    g_wbl[idx] = lo;
}

// ---------------------------------------------------------------------------
// Kernel 1: fused QKV projection. CTA: 128 rows x 192 cols. 384 threads,
// 12 warps (4M x 3N), warp tile 32x64. K chunks of 64.
// smem: AH 0, AL 18432, BH 36864, BL 64512; total 92160.
// ---------------------------------------------------------------------------
#define QA_H 0
#define QA_L 18432
#define QB_H 36864
#define QB_L 64512
#define Q_SMEM 92160

__global__ __launch_bounds__(384, 1) void qkv_gemm_fused(
    const float* __restrict__ x)
{
    extern __shared__ char sm[];
    const uint32_t smb = smem_u32(sm);

    const int tid  = threadIdx.x;
    const int wid  = tid >> 5;
    const int lane = tid & 31;
    const int row0 = blockIdx.x * 128;

    const int wm = wid & 3;          // 0..3
    const int wn = wid >> 2;         // 0..2  -> q / k / v
    const int m0 = wm * 32;
    const int n0 = wn * 64;          // row offset in B tile (192 rows)

    float c[2][8][4];
#pragma unroll
    for (int mt = 0; mt < 2; mt++)
#pragma unroll
        for (int nt = 0; nt < 8; nt++)
#pragma unroll
            for (int i = 0; i < 4; i++) c[mt][nt][i] = 0.f;

    const uint32_t a_row_off = (uint32_t)(m0 + (lane & 15)) * RS2
                             + (uint32_t)(lane >> 4) * 16;
    const uint32_t b_row_off = (uint32_t)(n0 + ((lane >> 4) & 1) * 8 + (lane & 7)) * RS2
                             + (uint32_t)((lane >> 3) & 1) * 16;

    const float4* x4 = (const float4*)x;

    for (int ch = 0; ch < 8; ch++) {
        const int c0 = ch * 64;

        // ---- x tile [128][64] fp32 -> bf16 hi/lo ----
        for (int idx = tid; idx < 2048; idx += 384) {
            int r  = idx >> 4;
            int c4 = idx & 15;
            float4 v = x4[(size_t)(row0 + r) * 128 + (c0 >> 2) + c4];

            __nv_bfloat16 h0 = __float2bfloat16(v.x);
            __nv_bfloat16 h1 = __float2bfloat16(v.y);
            __nv_bfloat16 h2 = __float2bfloat16(v.z);
            __nv_bfloat16 h3 = __float2bfloat16(v.w);
            __nv_bfloat16 l0 = __float2bfloat16(v.x - __bfloat162float(h0));
            __nv_bfloat16 l1 = __float2bfloat16(v.y - __bfloat162float(h1));
            __nv_bfloat16 l2 = __float2bfloat16(v.z - __bfloat162float(h2));
            __nv_bfloat16 l3 = __float2bfloat16(v.w - __bfloat162float(h3));

            uint32_t hA = ((uint32_t)__bfloat16_as_ushort(h1) << 16) | __bfloat16_as_ushort(h0);
            uint32_t hB = ((uint32_t)__bfloat16_as_ushort(h3) << 16) | __bfloat16_as_ushort(h2);
            uint32_t lA = ((uint32_t)__bfloat16_as_ushort(l1) << 16) | __bfloat16_as_ushort(l0);
            uint32_t lB = ((uint32_t)__bfloat16_as_ushort(l3) << 16) | __bfloat16_as_ushort(l2);

            uint32_t off = (uint32_t)r * RS2 + (uint32_t)c4 * 8;
            *(uint2*)(sm + QA_H + off) = make_uint2(hA, hB);
            *(uint2*)(sm + QA_L + off) = make_uint2(lA, lB);
        }

        // ---- B tiles: copy pre-converted W slices (192 rows x 64 halves) ----
        for (int idx = tid; idx < 1536; idx += 384) {
            int n    = idx >> 3;      // 0..191
            int part = idx & 7;
            size_t gsrc = ((size_t)n * C_ + c0 + part * 8);  // halves
            uint32_t off = (uint32_t)n * RS2 + (uint32_t)part * 16;
            *(uint4*)(sm + QB_H + off) = *(const uint4*)((const char*)g_wbh + gsrc * 2);
            *(uint4*)(sm + QB_L + off) = *(const uint4*)((const char*)g_wbl + gsrc * 2);
        }
        __syncthreads();

        // ---- mma over 4 k-steps of 16 ----
#pragma unroll
        for (int ks = 0; ks < 4; ks++) {
            uint32_t a_hi[2][4], a_lo[2][4];
#pragma unroll
            for (int mt = 0; mt < 2; mt++) {
                uint32_t off = a_row_off + (uint32_t)mt * 16 * RS2 + (uint32_t)ks * 32;
                ldsm_x4(a_hi[mt][0], a_hi[mt][1], a_hi[mt][2], a_hi[mt][3],
                        smb + QA_H + off);
                ldsm_x4(a_lo[mt][0], a_lo[mt][1], a_lo[mt][2], a_lo[mt][3],
                        smb + QA_L + off);
            }
            uint32_t b_hi[8][2], b_lo[8][2];
#pragma unroll
            for (int np = 0; np < 4; np++) {
                uint32_t off = b_row_off + (uint32_t)np * 16 * RS2 + (uint32_t)ks * 32;
                ldsm_x4(b_hi[np*2][0], b_hi[np*2][1], b_hi[np*2+1][0], b_hi[np*2+1][1],
                        smb + QB_H + off);
                ldsm_x4(b_lo[np*2][0], b_lo[np*2][1], b_lo[np*2+1][0], b_lo[np*2+1][1],
                        smb + QB_L + off);
            }
#pragma unroll
            for (int mt = 0; mt < 2; mt++)
#pragma unroll
                for (int nt = 0; nt < 8; nt++) {
                    mma_bf16(c[mt][nt], a_hi[mt], b_hi[nt]);
                    mma_bf16(c[mt][nt], a_hi[mt], b_lo[nt]);
                    mma_bf16(c[mt][nt], a_lo[mt], b_hi[nt]);
                }
        }
        __syncthreads();
    }

    // ---- epilogue: write hi/lo bf16; q pre-scaled by C^-0.5 ----
    const float SCALE = 0.04419417382415922f;
    const float mul = (wn == 0) ? SCALE : 1.0f;
    __nv_bfloat16* oh = (wn == 0) ? g_qh : (wn == 1) ? g_kh : g_vh;
    __nv_bfloat16* ol = (wn == 0) ? g_ql : (wn == 1) ? g_kl : g_vl;

    const int g  = lane >> 2;
    const int tg = lane & 3;
#pragma unroll
    for (int mt = 0; mt < 2; mt++)
#pragma unroll
        for (int nt = 0; nt < 8; nt++) {
            int col = nt * 8 + tg * 2;
#pragma unroll
            for (int rr = 0; rr < 2; rr++) {
                int row = row0 + m0 + mt * 16 + g + rr * 8;
                float v0 = c[mt][nt][rr * 2 + 0] * mul;
                float v1 = c[mt][nt][rr * 2 + 1] * mul;
                __nv_bfloat16 h0 = __float2bfloat16(v0);
                __nv_bfloat16 h1 = __float2bfloat16(v1);
                __nv_bfloat16 l0 = __float2bfloat16(v0 - __bfloat162float(h0));
                __nv_bfloat16 l1 = __float2bfloat16(v1 - __bfloat162float(h1));
                size_t o = (size_t)row * H_ + col;
                *(uint32_t*)(oh + o) = ((uint32_t)__bfloat16_as_ushort(h1) << 16)
                                     | __bfloat16_as_ushort(h0);
                *(uint32_t*)(ol + o) = ((uint32_t)__bfloat16_as_ushort(l1) << 16)
                                     | __bfloat16_as_ushort(l0);
            }
        }
}

// ---------------------------------------------------------------------------
// Kernel 2: tensor-core causal flash attention.
// block = (b, q-tile of 64), 128 threads = 4 warps, warp = 16 q rows.
// smem: QH 0, QL 9216, KH 18432, KL 27648, VH 36864, VL 46080 (55296 B)
// ---------------------------------------------------------------------------
#define AQ_H 0
#define AQ_L 9216
#define AK_H 18432
#define AK_L 27648
#define AV_H 36864
#define AV_L 46080
#define A_SMEM 55296

__global__ __launch_bounds__(128, 1) void attn_mma(float* __restrict__ out)
{
    extern __shared__ char sm[];
    const uint32_t smb = smem_u32(sm);

    const int b    = blockIdx.x;
    const int qt   = (T_ / 64 - 1) - blockIdx.y;   // heavy tiles first
    const int tid  = threadIdx.x;
    const int w    = tid >> 5;       // warp: q rows w*16..w*16+15
    const int lane = tid & 31;
    const int g    = lane >> 2;
    const int tg   = lane & 3;

    // ---- load Q tile (hi/lo) ----
    {
        const size_t base = ((size_t)b * T_ + qt * 64) * H_;   // halves
        for (int idx = tid; idx < 512; idx += 128) {
            int r = idx >> 3, part = idx & 7;
            size_t gs = base + (size_t)r * H_ + part * 8;
            uint32_t off = (uint32_t)r * RS2 + part * 16;
            *(uint4*)(sm + AQ_H + off) = *(const uint4*)((const char*)g_qh + gs * 2);
            *(uint4*)(sm + AQ_L + off) = *(const uint4*)((const char*)g_ql + gs * 2);
        }
    }
    __syncthreads();

    // ---- preload Q A-frags (4 k-steps) ----
    uint32_t qa_h[4][4], qa_l[4][4];
    {
        uint32_t a_row_off = (uint32_t)(w * 16 + (lane & 15)) * RS2
                           + (uint32_t)(lane >> 4) * 16;
#pragma unroll
        for (int ks = 0; ks < 4; ks++) {
            ldsm_x4(qa_h[ks][0], qa_h[ks][1], qa_h[ks][2], qa_h[ks][3],
                    smb + AQ_H + a_row_off + ks * 32);
            ldsm_x4(qa_l[ks][0], qa_l[ks][1], qa_l[ks][2], qa_l[ks][3],
                    smb + AQ_L + a_row_off + ks * 32);
        }
    }

    float o[8][4];
#pragma unroll
    for (int nt = 0; nt < 8; nt++)
#pragma unroll
        for (int i = 0; i < 4; i++) o[nt][i] = 0.f;
    float m0r = -INFINITY, m1r = -INFINITY;
    float l0r = 0.f, l1r = 0.f;

    const uint32_t kb_off = (uint32_t)(((lane >> 4) & 1) * 8 + (lane & 7)) * RS2
                          + (uint32_t)((lane >> 3) & 1) * 16;
    const uint32_t vb_off = (uint32_t)(((lane >> 3) & 1) * 8 + (lane & 7)) * RS2
                          + (uint32_t)((lane >> 4) & 1) * 16;

    for (int kt = 0; kt <= qt; kt++) {
        __syncthreads();   // protect smem from previous iteration's readers
        // ---- load K/V tiles (hi/lo) ----
        {
            const size_t base = ((size_t)b * T_ + kt * 64) * H_;
            for (int idx = tid; idx < 512; idx += 128) {
                int r = idx >> 3, part = idx & 7;
                size_t gs = base + (size_t)r * H_ + part * 8;
                uint32_t off = (uint32_t)r * RS2 + part * 16;
                *(uint4*)(sm + AK_H + off) = *(const uint4*)((const char*)g_kh + gs * 2);
                *(uint4*)(sm + AK_L + off) = *(const uint4*)((const char*)g_kl + gs * 2);
                *(uint4*)(sm + AV_H + off) = *(const uint4*)((const char*)g_vh + gs * 2);
                *(uint4*)(sm + AV_L + off) = *(const uint4*)((const char*)g_vl + gs * 2);
            }
        }
        __syncthreads();

        // ---- S = Q K^T (scaled; scale folded into q) ----
        float s[8][4];
#pragma unroll
        for (int nt = 0; nt < 8; nt++)
#pragma unroll
            for (int i = 0; i < 4; i++) s[nt][i] = 0.f;

#pragma unroll
        for (int ks = 0; ks < 4; ks++) {
            uint32_t b_hi[8][2], b_lo[8][2];
#pragma unroll
            for (int np = 0; np < 4; np++) {
                uint32_t off = kb_off + (uint32_t)np * 16 * RS2 + (uint32_t)ks * 32;
                ldsm_x4(b_hi[np*2][0], b_hi[np*2][1], b_hi[np*2+1][0], b_hi[np*2+1][1],
                        smb + AK_H + off);
                ldsm_x4(b_lo[np*2][0], b_lo[np*2][1], b_lo[np*2+1][0], b_lo[np*2+1][1],
                        smb + AK_L + off);
            }
#pragma unroll
            for (int nt = 0; nt < 8; nt++) {
                mma_bf16(s[nt], qa_h[ks], b_hi[nt]);
                mma_bf16(s[nt], qa_h[ks], b_lo[nt]);
                mma_bf16(s[nt], qa_l[ks], b_hi[nt]);
            }
        }

        // ---- causal mask on diagonal tile ----
        if (kt == qt) {
            const int q0 = w * 16 + g;        // local q row (row 0)
#pragma unroll
            for (int nt = 0; nt < 8; nt++) {
                int s0 = nt * 8 + tg * 2;     // local key col
                if (s0 > q0)     s[nt][0] = -1e30f;
                if (s0 + 1 > q0) s[nt][1] = -1e30f;
                if (s0 > q0 + 8)     s[nt][2] = -1e30f;
                if (s0 + 1 > q0 + 8) s[nt][3] = -1e30f;
            }
        }

        // ---- online softmax (rows g and g+8) ----
        float mt0 = -INFINITY, mt1 = -INFINITY;
#pragma unroll
        for (int nt = 0; nt < 8; nt++) {
            mt0 = fmaxf(mt0, fmaxf(s[nt][0], s[nt][1]));
            mt1 = fmaxf(mt1, fmaxf(s[nt][2], s[nt][3]));
        }
        mt0 = fmaxf(mt0, __shfl_xor_sync(0xffffffff, mt0, 1));
        mt0 = fmaxf(mt0, __shfl_xor_sync(0xffffffff, mt0, 2));
        mt1 = fmaxf(mt1, __shfl_xor_sync(0xffffffff, mt1, 1));
        mt1 = fmaxf(mt1, __shfl_xor_sync(0xffffffff, mt1, 2));

        float mn0 = fmaxf(m0r, mt0);
        float mn1 = fmaxf(m1r, mt1);
        float cr0 = __expf(m0r - mn0);
        float cr1 = __expf(m1r - mn1);
        m0r = mn0; m1r = mn1;

        float ls0 = 0.f, ls1 = 0.f;
#pragma unroll
        for (int nt = 0; nt < 8; nt++) {
            s[nt][0] = __expf(s[nt][0] - mn0);
            s[nt][1] = __expf(s[nt][1] - mn0);
            s[nt][2] = __expf(s[nt][2] - mn1);
            s[nt][3] = __expf(s[nt][3] - mn1);
            ls0 += s[nt][0] + s[nt][1];
            ls1 += s[nt][2] + s[nt][3];
        }
        l0r = l0r * cr0 + ls0;
        l1r = l1r * cr1 + ls1;

        // rescale O
#pragma unroll
        for (int nt = 0; nt < 8; nt++) {
            o[nt][0] *= cr0; o[nt][1] *= cr0;
            o[nt][2] *= cr1; o[nt][3] *= cr1;
        }

        // ---- repack P -> A-frags (hi/lo) ----
        uint32_t pa_h[4][4], pa_l[4][4];
#pragma unroll
        for (int j = 0; j < 4; j++) {
            float p00 = s[2*j][0],   p01 = s[2*j][1];
            float p02 = s[2*j][2],   p03 = s[2*j][3];
            float p10 = s[2*j+1][0], p11 = s[2*j+1][1];
            float p12 = s[2*j+1][2], p13 = s[2*j+1][3];

            float h00 = __bfloat162float(__float2bfloat16(p00));
            float h01 = __bfloat162float(__float2bfloat16(p01));
            float h02 = __bfloat162float(__float2bfloat16(p02));
            float h03 = __bfloat162float(__float2bfloat16(p03));
            float h10 = __bfloat162float(__float2bfloat16(p10));
            float h11 = __bfloat162float(__float2bfloat16(p11));
            float h12 = __bfloat162float(__float2bfloat16(p12));
            float h13 = __bfloat162float(__float2bfloat16(p13));

            pa_h[j][0] = pack_bf16x2(h00, h01);
            pa_h[j][1] = pack_bf16x2(h02, h03);
            pa_h[j][2] = pack_bf16x2(h10, h11);
            pa_h[j][3] = pack_bf16x2(h12, h13);
            pa_l[j][0] = pack_bf16x2(p00 - h00, p01 - h01);
            pa_l[j][1] = pack_bf16x2(p02 - h02, p03 - h03);
            pa_l[j][2] = pack_bf16x2(p10 - h10, p11 - h11);
            pa_l[j][3] = pack_bf16x2(p12 - h12, p13 - h13);
        }

        // ---- O += P V  (V^T B-frags via ldmatrix.trans) ----
#pragma unroll
        for (int ks = 0; ks < 4; ks++) {
            uint32_t vb_h[8][2], vb_l[8][2];
#pragma unroll
            for (int nt2 = 0; nt2 < 4; nt2++) {
                uint32_t off = vb_off + (uint32_t)(ks * 16) * RS2 + (uint32_t)nt2 * 32;
                ldsm_x4_t(vb_h[nt2*2][0], vb_h[nt2*2][1], vb_h[nt2*2+1][0], vb_h[nt2*2+1][1],
                          smb + AV_H + off);
                ldsm_x4_t(vb_l[nt2*2][0], vb_l[nt2*2][1], vb_l[nt2*2+1][0], vb_l[nt2*2+1][1],
                          smb + AV_L + off);
            }
#pragma unroll
            for (int nt = 0; nt < 8; nt++) {
                mma_bf16(o[nt], pa_h[ks], vb_h[nt]);
                mma_bf16(o[nt], pa_h[ks], vb_l[nt]);
                mma_bf16(o[nt], pa_l[ks], vb_h[nt]);
            }
        }
    }

    // ---- finalize ----
    l0r += __shfl_xor_sync(0xffffffff, l0r, 1);
    l0r += __shfl_xor_sync(0xffffffff, l0r, 2);
    l1r += __shfl_xor_sync(0xffffffff, l1r, 1);
    l1r += __shfl_xor_sync(0xffffffff, l1r, 2);
    float inv0 = 1.f / l0r;
    float inv1 = 1.f / l1r;

    const int q0 = qt * 64 + w * 16 + g;
#pragma unroll
    for (int nt = 0; nt < 8; nt++) {
        int h = nt * 8 + tg * 2;
        *(float2*)&out[((size_t)b * T_ + q0) * H_ + h] =
            make_float2(o[nt][0] * inv0, o[nt][1] * inv0);
        *(float2*)&out[((size_t)b * T_ + q0 + 8) * H_ + h] =
            make_float2(o[nt][2] * inv1, o[nt][3] * inv1);
    }
}

// ---------------------------------------------------------------------------
extern "C" void kernel_launch(void* const* d_in, const int* in_sizes, int n_in,
                              void* d_out, int out_size)
{
    const float* x  = (const float*)d_in[0];
    const float* Wk = (const float*)d_in[1];
    const float* Wq = (const float*)d_in[2];
    const float* Wv = (const float*)d_in[3];
    float* out = (float*)d_out;

    cudaFuncSetAttribute(qkv_gemm_fused,
                         cudaFuncAttributeMaxDynamicSharedMemorySize, Q_SMEM);
    cudaFuncSetAttribute(attn_mma,
                         cudaFuncAttributeMaxDynamicSharedMemorySize, A_SMEM);

    wconv<<<(3 * H_ * C_ + 255) / 256, 256>>>(Wq, Wk, Wv);
    qkv_gemm_fused<<<BT_ / 128, 384, Q_SMEM>>>(x);

    dim3 g2(B_, T_ / 64);
    attn_mma<<<g2, 128, A_SMEM>>>(out);
}

// round 6
// speedup vs baseline: 2.2744x; 1.4968x over previous
#include <cuda_runtime.h>
#include <cuda_bf16.h>
#include <math.h>
#include <stdint.h>

#define B_   256
#define T_   256
#define C_   512
#define H_   64
#define BT_  (B_ * T_)

// projected q (pre-scaled), k, v as bf16 hi/lo pairs
__device__ __nv_bfloat16 g_qh[BT_ * H_];
__device__ __nv_bfloat16 g_ql[BT_ * H_];
__device__ __nv_bfloat16 g_kh[BT_ * H_];
__device__ __nv_bfloat16 g_kl[BT_ * H_];
__device__ __nv_bfloat16 g_vh[BT_ * H_];
__device__ __nv_bfloat16 g_vl[BT_ * H_];

// W in B-operand layout [w][n=64][k=512], bf16 hi/lo
__device__ __nv_bfloat16 g_wbh[3 * H_ * C_];
__device__ __nv_bfloat16 g_wbl[3 * H_ * C_];

// ---------------------------------------------------------------------------
// helpers
// ---------------------------------------------------------------------------
__device__ __forceinline__ uint32_t smem_u32(const void* p) {
    uint32_t a;
    asm("{ .reg .u64 t; cvta.to.shared.u64 t, %1; cvt.u32.u64 %0, t; }"
        : "=r"(a) : "l"(p));
    return a;
}

__device__ __forceinline__ void ldsm_x4(uint32_t& r0, uint32_t& r1,
                                        uint32_t& r2, uint32_t& r3,
                                        uint32_t addr) {
    asm volatile("ldmatrix.sync.aligned.m8n8.x4.shared.b16 {%0,%1,%2,%3}, [%4];"
                 : "=r"(r0), "=r"(r1), "=r"(r2), "=r"(r3) : "r"(addr));
}

__device__ __forceinline__ void ldsm_x4_t(uint32_t& r0, uint32_t& r1,
                                          uint32_t& r2, uint32_t& r3,
                                          uint32_t addr) {
    asm volatile("ldmatrix.sync.aligned.m8n8.x4.trans.shared.b16 {%0,%1,%2,%3}, [%4];"
                 : "=r"(r0), "=r"(r1), "=r"(r2), "=r"(r3) : "r"(addr));
}

__device__ __forceinline__ void mma_bf16(float* c, const uint32_t* a,
                                         const uint32_t* b) {
    asm volatile(
        "mma.sync.aligned.m16n8k16.row.col.f32.bf16.bf16.f32 "
        "{%0,%1,%2,%3}, {%4,%5,%6,%7}, {%8,%9}, {%0,%1,%2,%3};"
        : "+f"(c[0]), "+f"(c[1]), "+f"(c[2]), "+f"(c[3])
        : "r"(a[0]), "r"(a[1]), "r"(a[2]), "r"(a[3]),
          "r"(b[0]), "r"(b[1]));
}

__device__ __forceinline__ uint32_t pack_bf16x2(float lo, float hi) {
    __nv_bfloat162 t = __floats2bfloat162_rn(lo, hi);
    return *(uint32_t*)&t;
}

__device__ __forceinline__ void cp_async16(uint32_t smem_addr, const void* gptr) {
    asm volatile("cp.async.cg.shared.global [%0], [%1], 16;"
                 :: "r"(smem_addr), "l"(gptr));
}
#define CP_COMMIT()  asm volatile("cp.async.commit_group;")
#define CP_WAIT(N)   asm volatile("cp.async.wait_group %0;" :: "n"(N))

#define RS2 144   // smem row stride in bytes (72 halves)

// ---------------------------------------------------------------------------
// Kernel 0: W -> bf16 hi/lo in [w][h][c] layout
// ---------------------------------------------------------------------------
__global__ void wconv(const float* __restrict__ Wq,
                      const float* __restrict__ Wk,
                      const float* __restrict__ Wv)
{
    int idx = blockIdx.x * 256 + threadIdx.x;
    if (idx >= 3 * H_ * C_) return;
    int w = idx / (H_ * C_);
    int r = idx % (H_ * C_);
    int h = r / C_;
    int c = r % C_;
    const float* W = (w == 0) ? Wq : (w == 1) ? Wk : Wv;
    float v = W[(size_t)c * H_ + h];
    __nv_bfloat16 hi = __float2bfloat16(v);
    __nv_bfloat16 lo = __float2bfloat16(v - __bfloat162float(hi));
    g_wbh[idx] = hi;
    g_wbl[idx] = lo;
}

// ---------------------------------------------------------------------------
// Kernel 1: pipelined fused QKV projection.
// CTA: 64 rows x 192 cols, 256 threads, 8 warps (2M x 4N), warp tile 32x48.
// K = 512 in 8 chunks of 64. W tiles double-buffered via cp.async;
// x prefetched into registers one chunk ahead.
// smem: AH 0 (9216), AL 9216, BH0 18432 (27648), BL0 46080,
//       BH1 73728, BL1 101376; total 129024
// ---------------------------------------------------------------------------
#define QK_AH  0
#define QK_AL  9216
#define QK_BH0 18432
#define QK_BL0 46080
#define QK_BH1 73728
#define QK_BL1 101376
#define QK_SMEM 129024

__global__ __launch_bounds__(256, 1) void qkv_gemm_pipe(
    const float* __restrict__ x)
{
    extern __shared__ char sm[];
    const uint32_t smb = smem_u32(sm);

    const int tid  = threadIdx.x;
    const int wid  = tid >> 5;
    const int lane = tid & 31;
    const int row0 = blockIdx.x * 64;

    const int wm = wid & 1;
    const int wn = wid >> 1;          // 0..3
    const int m0 = wm * 32;
    const int n0 = wn * 48;

    float c[2][6][4];
#pragma unroll
    for (int mt = 0; mt < 2; mt++)
#pragma unroll
        for (int nt = 0; nt < 6; nt++)
#pragma unroll
            for (int i = 0; i < 4; i++) c[mt][nt][i] = 0.f;

    const uint32_t a_row_off = (uint32_t)(m0 + (lane & 15)) * RS2
                             + (uint32_t)(lane >> 4) * 16;
    const uint32_t b_row_off = (uint32_t)(n0 + ((lane >> 4) & 1) * 8 + (lane & 7)) * RS2
                             + (uint32_t)((lane >> 3) & 1) * 16;

    const float4* x4 = (const float4*)x;

    // --- prologue: issue cp.async for B chunk 0, load x chunk 0 into regs ---
    {
        const int c0 = 0;
#pragma unroll
        for (int it = 0; it < 6; it++) {
            int idx = tid + it * 256;          // 0..1535
            int n = idx >> 3, part = idx & 7;
            size_t gs = ((size_t)n * C_ + c0) * 2 + (size_t)part * 16;
            uint32_t off = (uint32_t)n * RS2 + (uint32_t)part * 16;
            cp_async16(smb + QK_BH0 + off, (const char*)g_wbh + gs);
            cp_async16(smb + QK_BL0 + off, (const char*)g_wbl + gs);
        }
        CP_COMMIT();
    }

    float4 xv[4];
#pragma unroll
    for (int it = 0; it < 4; it++) {
        int idx = tid + it * 256;               // 0..1023
        int r = idx >> 4, c4 = idx & 15;
        xv[it] = x4[(size_t)(row0 + r) * 128 + c4];
    }

    for (int ch = 0; ch < 8; ch++) {
        // ---- convert x regs -> A hi/lo smem ----
#pragma unroll
        for (int it = 0; it < 4; it++) {
            int idx = tid + it * 256;
            int r = idx >> 4, c4 = idx & 15;
            float4 v = xv[it];

            __nv_bfloat16 h0 = __float2bfloat16(v.x);
            __nv_bfloat16 h1 = __float2bfloat16(v.y);
            __nv_bfloat16 h2 = __float2bfloat16(v.z);
            __nv_bfloat16 h3 = __float2bfloat16(v.w);
            __nv_bfloat16 l0 = __float2bfloat16(v.x - __bfloat162float(h0));
            __nv_bfloat16 l1 = __float2bfloat16(v.y - __bfloat162float(h1));
            __nv_bfloat16 l2 = __float2bfloat16(v.z - __bfloat162float(h2));
            __nv_bfloat16 l3 = __float2bfloat16(v.w - __bfloat162float(h3));

            uint32_t hA = ((uint32_t)__bfloat16_as_ushort(h1) << 16) | __bfloat16_as_ushort(h0);
            uint32_t hB = ((uint32_t)__bfloat16_as_ushort(h3) << 16) | __bfloat16_as_ushort(h2);
            uint32_t lA = ((uint32_t)__bfloat16_as_ushort(l1) << 16) | __bfloat16_as_ushort(l0);
            uint32_t lB = ((uint32_t)__bfloat16_as_ushort(l3) << 16) | __bfloat16_as_ushort(l2);

            uint32_t off = (uint32_t)r * RS2 + (uint32_t)c4 * 8;
            *(uint2*)(sm + QK_AH + off) = make_uint2(hA, hB);
            *(uint2*)(sm + QK_AL + off) = make_uint2(lA, lB);
        }

        // ---- prefetch chunk ch+1 (x regs + B cp.async into other buffer) ----
        if (ch < 7) {
            const int c1 = (ch + 1) * 64;
#pragma unroll
            for (int it = 0; it < 4; it++) {
                int idx = tid + it * 256;
                int r = idx >> 4, c4 = idx & 15;
                xv[it] = x4[(size_t)(row0 + r) * 128 + (c1 >> 2) + c4];
            }
            const uint32_t bh = ((ch + 1) & 1) ? QK_BH1 : QK_BH0;
            const uint32_t bl = ((ch + 1) & 1) ? QK_BL1 : QK_BL0;
#pragma unroll
            for (int it = 0; it < 6; it++) {
                int idx = tid + it * 256;
                int n = idx >> 3, part = idx & 7;
                size_t gs = ((size_t)n * C_ + c1) * 2 + (size_t)part * 16;
                uint32_t off = (uint32_t)n * RS2 + (uint32_t)part * 16;
                cp_async16(smb + bh + off, (const char*)g_wbh + gs);
                cp_async16(smb + bl + off, (const char*)g_wbl + gs);
            }
            CP_COMMIT();
            CP_WAIT(1);   // chunk ch's group done; ch+1 in flight
        } else {
            CP_WAIT(0);
        }
        __syncthreads();

        // ---- mma over 4 k-steps ----
        const uint32_t bhb = (ch & 1) ? QK_BH1 : QK_BH0;
        const uint32_t blb = (ch & 1) ? QK_BL1 : QK_BL0;
#pragma unroll
        for (int ks = 0; ks < 4; ks++) {
            uint32_t a_hi[2][4], a_lo[2][4];
#pragma unroll
            for (int mt = 0; mt < 2; mt++) {
                uint32_t off = a_row_off + (uint32_t)mt * 16 * RS2 + (uint32_t)ks * 32;
                ldsm_x4(a_hi[mt][0], a_hi[mt][1], a_hi[mt][2], a_hi[mt][3],
                        smb + QK_AH + off);
                ldsm_x4(a_lo[mt][0], a_lo[mt][1], a_lo[mt][2], a_lo[mt][3],
                        smb + QK_AL + off);
            }
            uint32_t b_hi[6][2], b_lo[6][2];
#pragma unroll
            for (int np = 0; np < 3; np++) {
                uint32_t off = b_row_off + (uint32_t)np * 16 * RS2 + (uint32_t)ks * 32;
                ldsm_x4(b_hi[np*2][0], b_hi[np*2][1], b_hi[np*2+1][0], b_hi[np*2+1][1],
                        smb + bhb + off);
                ldsm_x4(b_lo[np*2][0], b_lo[np*2][1], b_lo[np*2+1][0], b_lo[np*2+1][1],
                        smb + blb + off);
            }
#pragma unroll
            for (int mt = 0; mt < 2; mt++)
#pragma unroll
                for (int nt = 0; nt < 6; nt++) {
                    mma_bf16(c[mt][nt], a_hi[mt], b_hi[nt]);
                    mma_bf16(c[mt][nt], a_hi[mt], b_lo[nt]);
                    mma_bf16(c[mt][nt], a_lo[mt], b_hi[nt]);
                }
        }
        __syncthreads();
    }

    // ---- epilogue: write hi/lo bf16; q pre-scaled by C^-0.5 ----
    const float SCALE = 0.04419417382415922f;
    const int g  = lane >> 2;
    const int tg = lane & 3;
#pragma unroll
    for (int nt = 0; nt < 6; nt++) {
        int col0 = n0 + nt * 8;
        int w = col0 >> 6;
        int h = (col0 & 63) + tg * 2;
        float mul = (w == 0) ? SCALE : 1.0f;
        __nv_bfloat16* oh = (w == 0) ? g_qh : (w == 1) ? g_kh : g_vh;
        __nv_bfloat16* ol = (w == 0) ? g_ql : (w == 1) ? g_kl : g_vl;
#pragma unroll
        for (int mt = 0; mt < 2; mt++)
#pragma unroll
            for (int rr = 0; rr < 2; rr++) {
                int row = row0 + m0 + mt * 16 + g + rr * 8;
                float v0 = c[mt][nt][rr * 2 + 0] * mul;
                float v1 = c[mt][nt][rr * 2 + 1] * mul;
                __nv_bfloat16 h0 = __float2bfloat16(v0);
                __nv_bfloat16 h1 = __float2bfloat16(v1);
                __nv_bfloat16 l0 = __float2bfloat16(v0 - __bfloat162float(h0));
                __nv_bfloat16 l1 = __float2bfloat16(v1 - __bfloat162float(h1));
                size_t o = (size_t)row * H_ + h;
                *(uint32_t*)(oh + o) = ((uint32_t)__bfloat16_as_ushort(h1) << 16)
                                     | __bfloat16_as_ushort(h0);
                *(uint32_t*)(ol + o) = ((uint32_t)__bfloat16_as_ushort(l1) << 16)
                                     | __bfloat16_as_ushort(l0);
            }
    }
}

// ---------------------------------------------------------------------------
// Kernel 2: tensor-core causal flash attention (unchanged from R5).
// ---------------------------------------------------------------------------
#define AQ_H 0
#define AQ_L 9216
#define AK_H 18432
#define AK_L 27648
#define AV_H 36864
#define AV_L 46080
#define A_SMEM 55296

__global__ __launch_bounds__(128, 1) void attn_mma(float* __restrict__ out)
{
    extern __shared__ char sm[];
    const uint32_t smb = smem_u32(sm);

    const int b    = blockIdx.x;
    const int qt   = (T_ / 64 - 1) - blockIdx.y;
    const int tid  = threadIdx.x;
    const int w    = tid >> 5;
    const int lane = tid & 31;
    const int g    = lane >> 2;
    const int tg   = lane & 3;

    {
        const size_t base = ((size_t)b * T_ + qt * 64) * H_;
        for (int idx = tid; idx < 512; idx += 128) {
            int r = idx >> 3, part = idx & 7;
            size_t gs = base + (size_t)r * H_ + part * 8;
            uint32_t off = (uint32_t)r * RS2 + part * 16;
            *(uint4*)(sm + AQ_H + off) = *(const uint4*)((const char*)g_qh + gs * 2);
            *(uint4*)(sm + AQ_L + off) = *(const uint4*)((const char*)g_ql + gs * 2);
        }
    }
    __syncthreads();

    uint32_t qa_h[4][4], qa_l[4][4];
    {
        uint32_t a_row_off = (uint32_t)(w * 16 + (lane & 15)) * RS2
                           + (uint32_t)(lane >> 4) * 16;
#pragma unroll
        for (int ks = 0; ks < 4; ks++) {
            ldsm_x4(qa_h[ks][0], qa_h[ks][1], qa_h[ks][2], qa_h[ks][3],
                    smb + AQ_H + a_row_off + ks * 32);
            ldsm_x4(qa_l[ks][0], qa_l[ks][1], qa_l[ks][2], qa_l[ks][3],
                    smb + AQ_L + a_row_off + ks * 32);
        }
    }

    float o[8][4];
#pragma unroll
    for (int nt = 0; nt < 8; nt++)
#pragma unroll
        for (int i = 0; i < 4; i++) o[nt][i] = 0.f;
    float m0r = -INFINITY, m1r = -INFINITY;
    float l0r = 0.f, l1r = 0.f;

    const uint32_t kb_off = (uint32_t)(((lane >> 4) & 1) * 8 + (lane & 7)) * RS2
                          + (uint32_t)((lane >> 3) & 1) * 16;
    const uint32_t vb_off = (uint32_t)(((lane >> 3) & 1) * 8 + (lane & 7)) * RS2
                          + (uint32_t)((lane >> 4) & 1) * 16;

    for (int kt = 0; kt <= qt; kt++) {
        __syncthreads();
        {
            const size_t base = ((size_t)b * T_ + kt * 64) * H_;
            for (int idx = tid; idx < 512; idx += 128) {
                int r = idx >> 3, part = idx & 7;
                size_t gs = base + (size_t)r * H_ + part * 8;
                uint32_t off = (uint32_t)r * RS2 + part * 16;
                *(uint4*)(sm + AK_H + off) = *(const uint4*)((const char*)g_kh + gs * 2);
                *(uint4*)(sm + AK_L + off) = *(const uint4*)((const char*)g_kl + gs * 2);
                *(uint4*)(sm + AV_H + off) = *(const uint4*)((const char*)g_vh + gs * 2);
                *(uint4*)(sm + AV_L + off) = *(const uint4*)((const char*)g_vl + gs * 2);
            }
        }
        __syncthreads();

        float s[8][4];
#pragma unroll
        for (int nt = 0; nt < 8; nt++)
#pragma unroll
            for (int i = 0; i < 4; i++) s[nt][i] = 0.f;

#pragma unroll
        for (int ks = 0; ks < 4; ks++) {
            uint32_t b_hi[8][2], b_lo[8][2];
#pragma unroll
            for (int np = 0; np < 4; np++) {
                uint32_t off = kb_off + (uint32_t)np * 16 * RS2 + (uint32_t)ks * 32;
                ldsm_x4(b_hi[np*2][0], b_hi[np*2][1], b_hi[np*2+1][0], b_hi[np*2+1][1],
                        smb + AK_H + off);
                ldsm_x4(b_lo[np*2][0], b_lo[np*2][1], b_lo[np*2+1][0], b_lo[np*2+1][1],
                        smb + AK_L + off);
            }
#pragma unroll
            for (int nt = 0; nt < 8; nt++) {
                mma_bf16(s[nt], qa_h[ks], b_hi[nt]);
                mma_bf16(s[nt], qa_h[ks], b_lo[nt]);
                mma_bf16(s[nt], qa_l[ks], b_hi[nt]);
            }
        }

        if (kt == qt) {
            const int q0 = w * 16 + g;
#pragma unroll
            for (int nt = 0; nt < 8; nt++) {
                int s0 = nt * 8 + tg * 2;
                if (s0 > q0)     s[nt][0] = -1e30f;
                if (s0 + 1 > q0) s[nt][1] = -1e30f;
                if (s0 > q0 + 8)     s[nt][2] = -1e30f;
                if (s0 + 1 > q0 + 8) s[nt][3] = -1e30f;
            }
        }

        float mt0 = -INFINITY, mt1 = -INFINITY;
#pragma unroll
        for (int nt = 0; nt < 8; nt++) {
            mt0 = fmaxf(mt0, fmaxf(s[nt][0], s[nt][1]));
            mt1 = fmaxf(mt1, fmaxf(s[nt][2], s[nt][3]));
        }
        mt0 = fmaxf(mt0, __shfl_xor_sync(0xffffffff, mt0, 1));
        mt0 = fmaxf(mt0, __shfl_xor_sync(0xffffffff, mt0, 2));
        mt1 = fmaxf(mt1, __shfl_xor_sync(0xffffffff, mt1, 1));
        mt1 = fmaxf(mt1, __shfl_xor_sync(0xffffffff, mt1, 2));

        float mn0 = fmaxf(m0r, mt0);
        float mn1 = fmaxf(m1r, mt1);
        float cr0 = __expf(m0r - mn0);
        float cr1 = __expf(m1r - mn1);
        m0r = mn0; m1r = mn1;

        float ls0 = 0.f, ls1 = 0.f;
#pragma unroll
        for (int nt = 0; nt < 8; nt++) {
            s[nt][0] = __expf(s[nt][0] - mn0);
            s[nt][1] = __expf(s[nt][1] - mn0);
            s[nt][2] = __expf(s[nt][2] - mn1);
            s[nt][3] = __expf(s[nt][3] - mn1);
            ls0 += s[nt][0] + s[nt][1];
            ls1 += s[nt][2] + s[nt][3];
        }
        l0r = l0r * cr0 + ls0;
        l1r = l1r * cr1 + ls1;

#pragma unroll
        for (int nt = 0; nt < 8; nt++) {
            o[nt][0] *= cr0; o[nt][1] *= cr0;
            o[nt][2] *= cr1; o[nt][3] *= cr1;
        }

        uint32_t pa_h[4][4], pa_l[4][4];
#pragma unroll
        for (int j = 0; j < 4; j++) {
            float p00 = s[2*j][0],   p01 = s[2*j][1];
            float p02 = s[2*j][2],   p03 = s[2*j][3];
            float p10 = s[2*j+1][0], p11 = s[2*j+1][1];
            float p12 = s[2*j+1][2], p13 = s[2*j+1][3];

            float h00 = __bfloat162float(__float2bfloat16(p00));
            float h01 = __bfloat162float(__float2bfloat16(p01));
            float h02 = __bfloat162float(__float2bfloat16(p02));
            float h03 = __bfloat162float(__float2bfloat16(p03));
            float h10 = __bfloat162float(__float2bfloat16(p10));
            float h11 = __bfloat162float(__float2bfloat16(p11));
            float h12 = __bfloat162float(__float2bfloat16(p12));
            float h13 = __bfloat162float(__float2bfloat16(p13));

            pa_h[j][0] = pack_bf16x2(h00, h01);
            pa_h[j][1] = pack_bf16x2(h02, h03);
            pa_h[j][2] = pack_bf16x2(h10, h11);
            pa_h[j][3] = pack_bf16x2(h12, h13);
            pa_l[j][0] = pack_bf16x2(p00 - h00, p01 - h01);
            pa_l[j][1] = pack_bf16x2(p02 - h02, p03 - h03);
            pa_l[j][2] = pack_bf16x2(p10 - h10, p11 - h11);
            pa_l[j][3] = pack_bf16x2(p12 - h12, p13 - h13);
        }

#pragma unroll
        for (int ks = 0; ks < 4; ks++) {
            uint32_t vb_h[8][2], vb_l[8][2];
#pragma unroll
            for (int nt2 = 0; nt2 < 4; nt2++) {
                uint32_t off = vb_off + (uint32_t)(ks * 16) * RS2 + (uint32_t)nt2 * 32;
                ldsm_x4_t(vb_h[nt2*2][0], vb_h[nt2*2][1], vb_h[nt2*2+1][0], vb_h[nt2*2+1][1],
                          smb + AV_H + off);
                ldsm_x4_t(vb_l[nt2*2][0], vb_l[nt2*2][1], vb_l[nt2*2+1][0], vb_l[nt2*2+1][1],
                          smb + AV_L + off);
            }
#pragma unroll
            for (int nt = 0; nt < 8; nt++) {
                mma_bf16(o[nt], pa_h[ks], vb_h[nt]);
                mma_bf16(o[nt], pa_h[ks], vb_l[nt]);
                mma_bf16(o[nt], pa_l[ks], vb_h[nt]);
            }
        }
    }

    l0r += __shfl_xor_sync(0xffffffff, l0r, 1);
    l0r += __shfl_xor_sync(0xffffffff, l0r, 2);
    l1r += __shfl_xor_sync(0xffffffff, l1r, 1);
    l1r += __shfl_xor_sync(0xffffffff, l1r, 2);
    float inv0 = 1.f / l0r;
    float inv1 = 1.f / l1r;

    const int q0 = qt * 64 + w * 16 + g;
#pragma unroll
    for (int nt = 0; nt < 8; nt++) {
        int h = nt * 8 + tg * 2;
        *(float2*)&out[((size_t)b * T_ + q0) * H_ + h] =
            make_float2(o[nt][0] * inv0, o[nt][1] * inv0);
        *(float2*)&out[((size_t)b * T_ + q0 + 8) * H_ + h] =
            make_float2(o[nt][2] * inv1, o[nt][3] * inv1);
    }
}

// ---------------------------------------------------------------------------
extern "C" void kernel_launch(void* const* d_in, const int* in_sizes, int n_in,
                              void* d_out, int out_size)
{
    const float* x  = (const float*)d_in[0];
    const float* Wk = (const float*)d_in[1];
    const float* Wq = (const float*)d_in[2];
    const float* Wv = (const float*)d_in[3];
    float* out = (float*)d_out;

    cudaFuncSetAttribute(qkv_gemm_pipe,
                         cudaFuncAttributeMaxDynamicSharedMemorySize, QK_SMEM);
    cudaFuncSetAttribute(attn_mma,
                         cudaFuncAttributeMaxDynamicSharedMemorySize, A_SMEM);

    wconv<<<(3 * H_ * C_ + 255) / 256, 256>>>(Wq, Wk, Wv);
    qkv_gemm_pipe<<<BT_ / 64, 256, QK_SMEM>>>(x);

    dim3 g2(B_, T_ / 64);
    attn_mma<<<g2, 128, A_SMEM>>>(out);
}

// round 7
// speedup vs baseline: 2.3276x; 1.0234x over previous
#include <cuda_runtime.h>
#include <cuda_bf16.h>
#include <math.h>
#include <stdint.h>

#define B_   256
#define T_   256
#define C_   512
#define H_   64
#define BT_  (B_ * T_)

// projected q (pre-scaled), k, v as bf16 hi/lo pairs
__device__ __nv_bfloat16 g_qh[BT_ * H_];
__device__ __nv_bfloat16 g_ql[BT_ * H_];
__device__ __nv_bfloat16 g_kh[BT_ * H_];
__device__ __nv_bfloat16 g_kl[BT_ * H_];
__device__ __nv_bfloat16 g_vh[BT_ * H_];
__device__ __nv_bfloat16 g_vl[BT_ * H_];

// W in B-operand layout [w][n=64][k=512], bf16 hi/lo
__device__ __nv_bfloat16 g_wbh[3 * H_ * C_];
__device__ __nv_bfloat16 g_wbl[3 * H_ * C_];

// ---------------------------------------------------------------------------
// helpers
// ---------------------------------------------------------------------------
__device__ __forceinline__ uint32_t smem_u32(const void* p) {
    uint32_t a;
    asm("{ .reg .u64 t; cvta.to.shared.u64 t, %1; cvt.u32.u64 %0, t; }"
        : "=r"(a) : "l"(p));
    return a;
}

__device__ __forceinline__ void ldsm_x4(uint32_t& r0, uint32_t& r1,
                                        uint32_t& r2, uint32_t& r3,
                                        uint32_t addr) {
    asm volatile("ldmatrix.sync.aligned.m8n8.x4.shared.b16 {%0,%1,%2,%3}, [%4];"
                 : "=r"(r0), "=r"(r1), "=r"(r2), "=r"(r3) : "r"(addr));
}

__device__ __forceinline__ void ldsm_x4_t(uint32_t& r0, uint32_t& r1,
                                          uint32_t& r2, uint32_t& r3,
                                          uint32_t addr) {
    asm volatile("ldmatrix.sync.aligned.m8n8.x4.trans.shared.b16 {%0,%1,%2,%3}, [%4];"
                 : "=r"(r0), "=r"(r1), "=r"(r2), "=r"(r3) : "r"(addr));
}

__device__ __forceinline__ void mma_bf16(float* c, const uint32_t* a,
                                         const uint32_t* b) {
    asm volatile(
        "mma.sync.aligned.m16n8k16.row.col.f32.bf16.bf16.f32 "
        "{%0,%1,%2,%3}, {%4,%5,%6,%7}, {%8,%9}, {%0,%1,%2,%3};"
        : "+f"(c[0]), "+f"(c[1]), "+f"(c[2]), "+f"(c[3])
        : "r"(a[0]), "r"(a[1]), "r"(a[2]), "r"(a[3]),
          "r"(b[0]), "r"(b[1]));
}

__device__ __forceinline__ uint32_t pack_bf16x2(float lo, float hi) {
    __nv_bfloat162 t = __floats2bfloat162_rn(lo, hi);
    return *(uint32_t*)&t;
}

__device__ __forceinline__ void cp_async16(uint32_t smem_addr, const void* gptr) {
    asm volatile("cp.async.cg.shared.global [%0], [%1], 16;"
                 :: "r"(smem_addr), "l"(gptr));
}
#define CP_COMMIT()  asm volatile("cp.async.commit_group;")
#define CP_WAIT(N)   asm volatile("cp.async.wait_group %0;" :: "n"(N))

#define RS2 144   // smem row stride in bytes (72 halves)

// ---------------------------------------------------------------------------
// Kernel 0: W -> bf16 hi/lo in [w][h][c] layout
// ---------------------------------------------------------------------------
__global__ void wconv(const float* __restrict__ Wq,
                      const float* __restrict__ Wk,
                      const float* __restrict__ Wv)
{
    int idx = blockIdx.x * 256 + threadIdx.x;
    if (idx >= 3 * H_ * C_) return;
    int w = idx / (H_ * C_);
    int r = idx % (H_ * C_);
    int h = r / C_;
    int c = r % C_;
    const float* W = (w == 0) ? Wq : (w == 1) ? Wk : Wv;
    float v = W[(size_t)c * H_ + h];
    __nv_bfloat16 hi = __float2bfloat16(v);
    __nv_bfloat16 lo = __float2bfloat16(v - __bfloat162float(hi));
    g_wbh[idx] = hi;
    g_wbl[idx] = lo;
}

// ---------------------------------------------------------------------------
// Kernel 1: pipelined fused QKV projection (unchanged from R6).
// ---------------------------------------------------------------------------
#define QK_AH  0
#define QK_AL  9216
#define QK_BH0 18432
#define QK_BL0 46080
#define QK_BH1 73728
#define QK_BL1 101376
#define QK_SMEM 129024

__global__ __launch_bounds__(256, 1) void qkv_gemm_pipe(
    const float* __restrict__ x)
{
    extern __shared__ char sm[];
    const uint32_t smb = smem_u32(sm);

    const int tid  = threadIdx.x;
    const int wid  = tid >> 5;
    const int lane = tid & 31;
    const int row0 = blockIdx.x * 64;

    const int wm = wid & 1;
    const int wn = wid >> 1;
    const int m0 = wm * 32;
    const int n0 = wn * 48;

    float c[2][6][4];
#pragma unroll
    for (int mt = 0; mt < 2; mt++)
#pragma unroll
        for (int nt = 0; nt < 6; nt++)
#pragma unroll
            for (int i = 0; i < 4; i++) c[mt][nt][i] = 0.f;

    const uint32_t a_row_off = (uint32_t)(m0 + (lane & 15)) * RS2
                             + (uint32_t)(lane >> 4) * 16;
    const uint32_t b_row_off = (uint32_t)(n0 + ((lane >> 4) & 1) * 8 + (lane & 7)) * RS2
                             + (uint32_t)((lane >> 3) & 1) * 16;

    const float4* x4 = (const float4*)x;

    {
        const int c0 = 0;
#pragma unroll
        for (int it = 0; it < 6; it++) {
            int idx = tid + it * 256;
            int n = idx >> 3, part = idx & 7;
            size_t gs = ((size_t)n * C_ + c0) * 2 + (size_t)part * 16;
            uint32_t off = (uint32_t)n * RS2 + (uint32_t)part * 16;
            cp_async16(smb + QK_BH0 + off, (const char*)g_wbh + gs);
            cp_async16(smb + QK_BL0 + off, (const char*)g_wbl + gs);
        }
        CP_COMMIT();
    }

    float4 xv[4];
#pragma unroll
    for (int it = 0; it < 4; it++) {
        int idx = tid + it * 256;
        int r = idx >> 4, c4 = idx & 15;
        xv[it] = x4[(size_t)(row0 + r) * 128 + c4];
    }

    for (int ch = 0; ch < 8; ch++) {
#pragma unroll
        for (int it = 0; it < 4; it++) {
            int idx = tid + it * 256;
            int r = idx >> 4, c4 = idx & 15;
            float4 v = xv[it];

            __nv_bfloat16 h0 = __float2bfloat16(v.x);
            __nv_bfloat16 h1 = __float2bfloat16(v.y);
            __nv_bfloat16 h2 = __float2bfloat16(v.z);
            __nv_bfloat16 h3 = __float2bfloat16(v.w);
            __nv_bfloat16 l0 = __float2bfloat16(v.x - __bfloat162float(h0));
            __nv_bfloat16 l1 = __float2bfloat16(v.y - __bfloat162float(h1));
            __nv_bfloat16 l2 = __float2bfloat16(v.z - __bfloat162float(h2));
            __nv_bfloat16 l3 = __float2bfloat16(v.w - __bfloat162float(h3));

            uint32_t hA = ((uint32_t)__bfloat16_as_ushort(h1) << 16) | __bfloat16_as_ushort(h0);
            uint32_t hB = ((uint32_t)__bfloat16_as_ushort(h3) << 16) | __bfloat16_as_ushort(h2);
            uint32_t lA = ((uint32_t)__bfloat16_as_ushort(l1) << 16) | __bfloat16_as_ushort(l0);
            uint32_t lB = ((uint32_t)__bfloat16_as_ushort(l3) << 16) | __bfloat16_as_ushort(l2);

            uint32_t off = (uint32_t)r * RS2 + (uint32_t)c4 * 8;
            *(uint2*)(sm + QK_AH + off) = make_uint2(hA, hB);
            *(uint2*)(sm + QK_AL + off) = make_uint2(lA, lB);
        }

        if (ch < 7) {
            const int c1 = (ch + 1) * 64;
#pragma unroll
            for (int it = 0; it < 4; it++) {
                int idx = tid + it * 256;
                int r = idx >> 4, c4 = idx & 15;
                xv[it] = x4[(size_t)(row0 + r) * 128 + (c1 >> 2) + c4];
            }
            const uint32_t bh = ((ch + 1) & 1) ? QK_BH1 : QK_BH0;
            const uint32_t bl = ((ch + 1) & 1) ? QK_BL1 : QK_BL0;
#pragma unroll
            for (int it = 0; it < 6; it++) {
                int idx = tid + it * 256;
                int n = idx >> 3, part = idx & 7;
                size_t gs = ((size_t)n * C_ + c1) * 2 + (size_t)part * 16;
                uint32_t off = (uint32_t)n * RS2 + (uint32_t)part * 16;
                cp_async16(smb + bh + off, (const char*)g_wbh + gs);
                cp_async16(smb + bl + off, (const char*)g_wbl + gs);
            }
            CP_COMMIT();
            CP_WAIT(1);
        } else {
            CP_WAIT(0);
        }
        __syncthreads();

        const uint32_t bhb = (ch & 1) ? QK_BH1 : QK_BH0;
        const uint32_t blb = (ch & 1) ? QK_BL1 : QK_BL0;
#pragma unroll
        for (int ks = 0; ks < 4; ks++) {
            uint32_t a_hi[2][4], a_lo[2][4];
#pragma unroll
            for (int mt = 0; mt < 2; mt++) {
                uint32_t off = a_row_off + (uint32_t)mt * 16 * RS2 + (uint32_t)ks * 32;
                ldsm_x4(a_hi[mt][0], a_hi[mt][1], a_hi[mt][2], a_hi[mt][3],
                        smb + QK_AH + off);
                ldsm_x4(a_lo[mt][0], a_lo[mt][1], a_lo[mt][2], a_lo[mt][3],
                        smb + QK_AL + off);
            }
            uint32_t b_hi[6][2], b_lo[6][2];
#pragma unroll
            for (int np = 0; np < 3; np++) {
                uint32_t off = b_row_off + (uint32_t)np * 16 * RS2 + (uint32_t)ks * 32;
                ldsm_x4(b_hi[np*2][0], b_hi[np*2][1], b_hi[np*2+1][0], b_hi[np*2+1][1],
                        smb + bhb + off);
                ldsm_x4(b_lo[np*2][0], b_lo[np*2][1], b_lo[np*2+1][0], b_lo[np*2+1][1],
                        smb + blb + off);
            }
#pragma unroll
            for (int mt = 0; mt < 2; mt++)
#pragma unroll
                for (int nt = 0; nt < 6; nt++) {
                    mma_bf16(c[mt][nt], a_hi[mt], b_hi[nt]);
                    mma_bf16(c[mt][nt], a_hi[mt], b_lo[nt]);
                    mma_bf16(c[mt][nt], a_lo[mt], b_hi[nt]);
                }
        }
        __syncthreads();
    }

    const float SCALE = 0.04419417382415922f;
    const int g  = lane >> 2;
    const int tg = lane & 3;
#pragma unroll
    for (int nt = 0; nt < 6; nt++) {
        int col0 = n0 + nt * 8;
        int w = col0 >> 6;
        int h = (col0 & 63) + tg * 2;
        float mul = (w == 0) ? SCALE : 1.0f;
        __nv_bfloat16* oh = (w == 0) ? g_qh : (w == 1) ? g_kh : g_vh;
        __nv_bfloat16* ol = (w == 0) ? g_ql : (w == 1) ? g_kl : g_vl;
#pragma unroll
        for (int mt = 0; mt < 2; mt++)
#pragma unroll
            for (int rr = 0; rr < 2; rr++) {
                int row = row0 + m0 + mt * 16 + g + rr * 8;
                float v0 = c[mt][nt][rr * 2 + 0] * mul;
                float v1 = c[mt][nt][rr * 2 + 1] * mul;
                __nv_bfloat16 h0 = __float2bfloat16(v0);
                __nv_bfloat16 h1 = __float2bfloat16(v1);
                __nv_bfloat16 l0 = __float2bfloat16(v0 - __bfloat162float(h0));
                __nv_bfloat16 l1 = __float2bfloat16(v1 - __bfloat162float(h1));
                size_t o = (size_t)row * H_ + h;
                *(uint32_t*)(oh + o) = ((uint32_t)__bfloat16_as_ushort(h1) << 16)
                                     | __bfloat16_as_ushort(h0);
                *(uint32_t*)(ol + o) = ((uint32_t)__bfloat16_as_ushort(l1) << 16)
                                     | __bfloat16_as_ushort(l0);
            }
    }
}

// ---------------------------------------------------------------------------
// Kernel 2: tensor-core causal flash attention, Q-tile 128, cp.async
// double-buffered K/V stages, per-warp causal skip.
// block = (b, q-tile of 128), 256 threads = 8 warps, warp = 16 q rows.
// smem: QH 0, QL 18432, stage0 @36864 (KH,KL,VH,VL x 9216), stage1 @73728.
// total 110592 B.
// ---------------------------------------------------------------------------
#define AT_QH 0
#define AT_QL 18432
#define AT_ST0 36864
#define AT_STAGE 36864
#define AT_KH 0
#define AT_KL 9216
#define AT_VH 18432
#define AT_VL 27648
#define A_SMEM 110592

__global__ __launch_bounds__(256, 1) void attn_mma(float* __restrict__ out)
{
    extern __shared__ char sm[];
    const uint32_t smb = smem_u32(sm);

    const int b    = blockIdx.x;
    const int qt   = 1 - blockIdx.y;          // heavy tile (qt=1) first
    const int tid  = threadIdx.x;
    const int w    = tid >> 5;                 // warp: q rows w*16..w*16+15
    const int lane = tid & 31;
    const int g    = lane >> 2;
    const int tg   = lane & 3;

    const int rowbase = qt * 128 + w * 16;     // global q row of this warp
    const int nkt = qt * 2 + 2;                // number of 64-key tiles

    // ---- load Q tile (128 rows, hi/lo) + prologue K/V stage 0 ----
    {
        const size_t base = ((size_t)b * T_ + qt * 128) * H_;   // halves
        for (int idx = tid; idx < 1024; idx += 256) {
            int r = idx >> 3, part = idx & 7;
            size_t gs = base + (size_t)r * H_ + part * 8;
            uint32_t off = (uint32_t)r * RS2 + part * 16;
            *(uint4*)(sm + AT_QH + off) = *(const uint4*)((const char*)g_qh + gs * 2);
            *(uint4*)(sm + AT_QL + off) = *(const uint4*)((const char*)g_ql + gs * 2);
        }
        const size_t kbase = ((size_t)b * T_) * H_;   // kt = 0
        const uint32_t stg = smb + AT_ST0;
        for (int idx = tid; idx < 512; idx += 256) {
            int r = idx >> 3, part = idx & 7;
            size_t gs2 = (kbase + (size_t)r * H_ + part * 8) * 2;  // bytes
            uint32_t off = (uint32_t)r * RS2 + part * 16;
            cp_async16(stg + AT_KH + off, (const char*)g_kh + gs2);
            cp_async16(stg + AT_KL + off, (const char*)g_kl + gs2);
            cp_async16(stg + AT_VH + off, (const char*)g_vh + gs2);
            cp_async16(stg + AT_VL + off, (const char*)g_vl + gs2);
        }
        CP_COMMIT();
    }
    __syncthreads();

    // ---- preload Q A-frags (4 k-steps) ----
    uint32_t qa_h[4][4], qa_l[4][4];
    {
        uint32_t a_row_off = (uint32_t)(w * 16 + (lane & 15)) * RS2
                           + (uint32_t)(lane >> 4) * 16;
#pragma unroll
        for (int ks = 0; ks < 4; ks++) {
            ldsm_x4(qa_h[ks][0], qa_h[ks][1], qa_h[ks][2], qa_h[ks][3],
                    smb + AT_QH + a_row_off + ks * 32);
            ldsm_x4(qa_l[ks][0], qa_l[ks][1], qa_l[ks][2], qa_l[ks][3],
                    smb + AT_QL + a_row_off + ks * 32);
        }
    }

    float o[8][4];
#pragma unroll
    for (int nt = 0; nt < 8; nt++)
#pragma unroll
        for (int i = 0; i < 4; i++) o[nt][i] = 0.f;
    float m0r = -INFINITY, m1r = -INFINITY;
    float l0r = 0.f, l1r = 0.f;

    const uint32_t kb_off = (uint32_t)(((lane >> 4) & 1) * 8 + (lane & 7)) * RS2
                          + (uint32_t)((lane >> 3) & 1) * 16;
    const uint32_t vb_off = (uint32_t)(((lane >> 3) & 1) * 8 + (lane & 7)) * RS2
                          + (uint32_t)((lane >> 4) & 1) * 16;

    for (int kt = 0; kt < nkt; kt++) {
        // prefetch kt+1 into the other stage, then wait for kt's data
        if (kt + 1 < nkt) {
            const size_t kbase = ((size_t)b * T_ + (kt + 1) * 64) * H_;
            const uint32_t stg = smb + AT_ST0 + ((kt + 1) & 1) * AT_STAGE;
            for (int idx = tid; idx < 512; idx += 256) {
                int r = idx >> 3, part = idx & 7;
                size_t gs2 = (kbase + (size_t)r * H_ + part * 8) * 2;
                uint32_t off = (uint32_t)r * RS2 + part * 16;
                cp_async16(stg + AT_KH + off, (const char*)g_kh + gs2);
                cp_async16(stg + AT_KL + off, (const char*)g_kl + gs2);
                cp_async16(stg + AT_VH + off, (const char*)g_vh + gs2);
                cp_async16(stg + AT_VL + off, (const char*)g_vl + gs2);
            }
            CP_COMMIT();
            CP_WAIT(1);
        } else {
            CP_WAIT(0);
        }
        __syncthreads();

        const int kcol0 = kt * 64;
        // per-warp causal skip: all keys beyond this warp's rows
        if (kcol0 <= rowbase + 15) {
            const uint32_t stg = smb + AT_ST0 + (kt & 1) * AT_STAGE;

            // ---- S = Q K^T ----
            float s[8][4];
#pragma unroll
            for (int nt = 0; nt < 8; nt++)
#pragma unroll
                for (int i = 0; i < 4; i++) s[nt][i] = 0.f;

#pragma unroll
            for (int ks = 0; ks < 4; ks++) {
                uint32_t b_hi[8][2], b_lo[8][2];
#pragma unroll
                for (int np = 0; np < 4; np++) {
                    uint32_t off = kb_off + (uint32_t)np * 16 * RS2 + (uint32_t)ks * 32;
                    ldsm_x4(b_hi[np*2][0], b_hi[np*2][1], b_hi[np*2+1][0], b_hi[np*2+1][1],
                            stg + AT_KH + off);
                    ldsm_x4(b_lo[np*2][0], b_lo[np*2][1], b_lo[np*2+1][0], b_lo[np*2+1][1],
                            stg + AT_KL + off);
                }
#pragma unroll
                for (int nt = 0; nt < 8; nt++) {
                    mma_bf16(s[nt], qa_h[ks], b_hi[nt]);
                    mma_bf16(s[nt], qa_h[ks], b_lo[nt]);
                    mma_bf16(s[nt], qa_l[ks], b_hi[nt]);
                }
            }

            // ---- causal mask (diagonal region) ----
            if (kcol0 + 63 > rowbase) {
                const int r0g = rowbase + g;
#pragma unroll
                for (int nt = 0; nt < 8; nt++) {
                    int cg = kcol0 + nt * 8 + tg * 2;
                    if (cg > r0g)         s[nt][0] = -1e30f;
                    if (cg + 1 > r0g)     s[nt][1] = -1e30f;
                    if (cg > r0g + 8)     s[nt][2] = -1e30f;
                    if (cg + 1 > r0g + 8) s[nt][3] = -1e30f;
                }
            }

            // ---- online softmax ----
            float mt0 = -INFINITY, mt1 = -INFINITY;
#pragma unroll
            for (int nt = 0; nt < 8; nt++) {
                mt0 = fmaxf(mt0, fmaxf(s[nt][0], s[nt][1]));
                mt1 = fmaxf(mt1, fmaxf(s[nt][2], s[nt][3]));
            }
            mt0 = fmaxf(mt0, __shfl_xor_sync(0xffffffff, mt0, 1));
            mt0 = fmaxf(mt0, __shfl_xor_sync(0xffffffff, mt0, 2));
            mt1 = fmaxf(mt1, __shfl_xor_sync(0xffffffff, mt1, 1));
            mt1 = fmaxf(mt1, __shfl_xor_sync(0xffffffff, mt1, 2));

            float mn0 = fmaxf(m0r, mt0);
            float mn1 = fmaxf(m1r, mt1);
            float cr0 = __expf(m0r - mn0);
            float cr1 = __expf(m1r - mn1);
            m0r = mn0; m1r = mn1;

            float ls0 = 0.f, ls1 = 0.f;
#pragma unroll
            for (int nt = 0; nt < 8; nt++) {
                s[nt][0] = __expf(s[nt][0] - mn0);
                s[nt][1] = __expf(s[nt][1] - mn0);
                s[nt][2] = __expf(s[nt][2] - mn1);
                s[nt][3] = __expf(s[nt][3] - mn1);
                ls0 += s[nt][0] + s[nt][1];
                ls1 += s[nt][2] + s[nt][3];
            }
            l0r = l0r * cr0 + ls0;
            l1r = l1r * cr1 + ls1;

#pragma unroll
            for (int nt = 0; nt < 8; nt++) {
                o[nt][0] *= cr0; o[nt][1] *= cr0;
                o[nt][2] *= cr1; o[nt][3] *= cr1;
            }

            // ---- repack P -> A-frags (hi/lo) ----
            uint32_t pa_h[4][4], pa_l[4][4];
#pragma unroll
            for (int j = 0; j < 4; j++) {
                float p00 = s[2*j][0],   p01 = s[2*j][1];
                float p02 = s[2*j][2],   p03 = s[2*j][3];
                float p10 = s[2*j+1][0], p11 = s[2*j+1][1];
                float p12 = s[2*j+1][2], p13 = s[2*j+1][3];

                float h00 = __bfloat162float(__float2bfloat16(p00));
                float h01 = __bfloat162float(__float2bfloat16(p01));
                float h02 = __bfloat162float(__float2bfloat16(p02));
                float h03 = __bfloat162float(__float2bfloat16(p03));
                float h10 = __bfloat162float(__float2bfloat16(p10));
                float h11 = __bfloat162float(__float2bfloat16(p11));
                float h12 = __bfloat162float(__float2bfloat16(p12));
                float h13 = __bfloat162float(__float2bfloat16(p13));

                pa_h[j][0] = pack_bf16x2(h00, h01);
                pa_h[j][1] = pack_bf16x2(h02, h03);
                pa_h[j][2] = pack_bf16x2(h10, h11);
                pa_h[j][3] = pack_bf16x2(h12, h13);
                pa_l[j][0] = pack_bf16x2(p00 - h00, p01 - h01);
                pa_l[j][1] = pack_bf16x2(p02 - h02, p03 - h03);
                pa_l[j][2] = pack_bf16x2(p10 - h10, p11 - h11);
                pa_l[j][3] = pack_bf16x2(p12 - h12, p13 - h13);
            }

            // ---- O += P V ----
#pragma unroll
            for (int ks = 0; ks < 4; ks++) {
                uint32_t vb_h[8][2], vb_l[8][2];
#pragma unroll
                for (int nt2 = 0; nt2 < 4; nt2++) {
                    uint32_t off = vb_off + (uint32_t)(ks * 16) * RS2 + (uint32_t)nt2 * 32;
                    ldsm_x4_t(vb_h[nt2*2][0], vb_h[nt2*2][1], vb_h[nt2*2+1][0], vb_h[nt2*2+1][1],
                              stg + AT_VH + off);
                    ldsm_x4_t(vb_l[nt2*2][0], vb_l[nt2*2][1], vb_l[nt2*2+1][0], vb_l[nt2*2+1][1],
                              stg + AT_VL + off);
                }
#pragma unroll
                for (int nt = 0; nt < 8; nt++) {
                    mma_bf16(o[nt], pa_h[ks], vb_h[nt]);
                    mma_bf16(o[nt], pa_h[ks], vb_l[nt]);
                    mma_bf16(o[nt], pa_l[ks], vb_h[nt]);
                }
            }
        }
        __syncthreads();
    }

    // ---- finalize ----
    l0r += __shfl_xor_sync(0xffffffff, l0r, 1);
    l0r += __shfl_xor_sync(0xffffffff, l0r, 2);
    l1r += __shfl_xor_sync(0xffffffff, l1r, 1);
    l1r += __shfl_xor_sync(0xffffffff, l1r, 2);
    float inv0 = 1.f / l0r;
    float inv1 = 1.f / l1r;

    const int q0 = rowbase + g;
#pragma unroll
    for (int nt = 0; nt < 8; nt++) {
        int h = nt * 8 + tg * 2;
        *(float2*)&out[((size_t)b * T_ + q0) * H_ + h] =
            make_float2(o[nt][0] * inv0, o[nt][1] * inv0);
        *(float2*)&out[((size_t)b * T_ + q0 + 8) * H_ + h] =
            make_float2(o[nt][2] * inv1, o[nt][3] * inv1);
    }
}

// ---------------------------------------------------------------------------
extern "C" void kernel_launch(void* const* d_in, const int* in_sizes, int n_in,
                              void* d_out, int out_size)
{
    const float* x  = (const float*)d_in[0];
    const float* Wk = (const float*)d_in[1];
    const float* Wq = (const float*)d_in[2];
    const float* Wv = (const float*)d_in[3];
    float* out = (float*)d_out;

    cudaFuncSetAttribute(qkv_gemm_pipe,
                         cudaFuncAttributeMaxDynamicSharedMemorySize, QK_SMEM);
    cudaFuncSetAttribute(attn_mma,
                         cudaFuncAttributeMaxDynamicSharedMemorySize, A_SMEM);

    wconv<<<(3 * H_ * C_ + 255) / 256, 256>>>(Wq, Wk, Wv);
    qkv_gemm_pipe<<<BT_ / 64, 256, QK_SMEM>>>(x);

    dim3 g2(B_, T_ / 128);
    attn_mma<<<g2, 256, A_SMEM>>>(out);
}

// round 8
// speedup vs baseline: 6.1123x; 2.6260x over previous
#include <cuda_runtime.h>
#include <cuda_fp16.h>
#include <math.h>
#include <stdint.h>

#define B_   256
#define T_   256
#define C_   512
#define H_   64
#define BT_  (B_ * T_)

// projected q (pre-scaled by C^-0.5), k, v as fp16
__device__ __half g_q16[BT_ * H_];
__device__ __half g_k16[BT_ * H_];
__device__ __half g_v16[BT_ * H_];

// W in B-operand layout [w][n=64][k=512], fp16
__device__ __half g_w16[3 * H_ * C_];

// ---------------------------------------------------------------------------
// helpers
// ---------------------------------------------------------------------------
__device__ __forceinline__ uint32_t smem_u32(const void* p) {
    uint32_t a;
    asm("{ .reg .u64 t; cvta.to.shared.u64 t, %1; cvt.u32.u64 %0, t; }"
        : "=r"(a) : "l"(p));
    return a;
}

__device__ __forceinline__ void ldsm_x4(uint32_t& r0, uint32_t& r1,
                                        uint32_t& r2, uint32_t& r3,
                                        uint32_t addr) {
    asm volatile("ldmatrix.sync.aligned.m8n8.x4.shared.b16 {%0,%1,%2,%3}, [%4];"
                 : "=r"(r0), "=r"(r1), "=r"(r2), "=r"(r3) : "r"(addr));
}

__device__ __forceinline__ void ldsm_x4_t(uint32_t& r0, uint32_t& r1,
                                          uint32_t& r2, uint32_t& r3,
                                          uint32_t addr) {
    asm volatile("ldmatrix.sync.aligned.m8n8.x4.trans.shared.b16 {%0,%1,%2,%3}, [%4];"
                 : "=r"(r0), "=r"(r1), "=r"(r2), "=r"(r3) : "r"(addr));
}

__device__ __forceinline__ void mma_f16(float* c, const uint32_t* a,
                                        const uint32_t* b) {
    asm volatile(
        "mma.sync.aligned.m16n8k16.row.col.f32.f16.f16.f32 "
        "{%0,%1,%2,%3}, {%4,%5,%6,%7}, {%8,%9}, {%0,%1,%2,%3};"
        : "+f"(c[0]), "+f"(c[1]), "+f"(c[2]), "+f"(c[3])
        : "r"(a[0]), "r"(a[1]), "r"(a[2]), "r"(a[3]),
          "r"(b[0]), "r"(b[1]));
}

__device__ __forceinline__ uint32_t pack_h2(float lo, float hi) {
    __half2 t = __floats2half2_rn(lo, hi);
    return *(uint32_t*)&t;
}

__device__ __forceinline__ void cp_async16(uint32_t smem_addr, const void* gptr) {
    asm volatile("cp.async.cg.shared.global [%0], [%1], 16;"
                 :: "r"(smem_addr), "l"(gptr));
}
#define CP_COMMIT()  asm volatile("cp.async.commit_group;")
#define CP_WAIT(N)   asm volatile("cp.async.wait_group %0;" :: "n"(N))

#define RS2 144   // smem row stride in bytes (72 halves)

// ---------------------------------------------------------------------------
// Kernel 0: W -> fp16 in [w][h][c] layout
// ---------------------------------------------------------------------------
__global__ void wconv(const float* __restrict__ Wq,
                      const float* __restrict__ Wk,
                      const float* __restrict__ Wv)
{
    int idx = blockIdx.x * 256 + threadIdx.x;
    if (idx >= 3 * H_ * C_) return;
    int w = idx / (H_ * C_);
    int r = idx % (H_ * C_);
    int h = r / C_;
    int c = r % C_;
    const float* W = (w == 0) ? Wq : (w == 1) ? Wk : Wv;
    g_w16[idx] = __float2half(W[(size_t)c * H_ + h]);
}

// ---------------------------------------------------------------------------
// Kernel 1: pipelined fused QKV projection, single-term fp16.
// CTA: 64 rows x 192 cols, 256 threads, 8 warps (2M x 4N), warp tile 32x48.
// K = 512 in 8 chunks of 64. W tiles double-buffered via cp.async;
// x prefetched into registers one chunk ahead.
// smem: A 0 (9216), B0 9216 (27648), B1 36864 (27648); total 64512
// ---------------------------------------------------------------------------
#define QK_A  0
#define QK_B0 9216
#define QK_B1 36864
#define QK_SMEM 64512

__global__ __launch_bounds__(256, 2) void qkv_gemm_pipe(
    const float* __restrict__ x)
{
    extern __shared__ char sm[];
    const uint32_t smb = smem_u32(sm);

    const int tid  = threadIdx.x;
    const int wid  = tid >> 5;
    const int lane = tid & 31;
    const int row0 = blockIdx.x * 64;

    const int wm = wid & 1;
    const int wn = wid >> 1;          // 0..3
    const int m0 = wm * 32;
    const int n0 = wn * 48;

    float c[2][6][4];
#pragma unroll
    for (int mt = 0; mt < 2; mt++)
#pragma unroll
        for (int nt = 0; nt < 6; nt++)
#pragma unroll
            for (int i = 0; i < 4; i++) c[mt][nt][i] = 0.f;

    const uint32_t a_row_off = (uint32_t)(m0 + (lane & 15)) * RS2
                             + (uint32_t)(lane >> 4) * 16;
    const uint32_t b_row_off = (uint32_t)(n0 + ((lane >> 4) & 1) * 8 + (lane & 7)) * RS2
                             + (uint32_t)((lane >> 3) & 1) * 16;

    const float4* x4 = (const float4*)x;

    // prologue: B chunk 0 via cp.async, x chunk 0 into regs
    {
#pragma unroll
        for (int it = 0; it < 6; it++) {
            int idx = tid + it * 256;          // 0..1535
            int n = idx >> 3, part = idx & 7;
            size_t gs = ((size_t)n * C_) * 2 + (size_t)part * 16;
            uint32_t off = (uint32_t)n * RS2 + (uint32_t)part * 16;
            cp_async16(smb + QK_B0 + off, (const char*)g_w16 + gs);
        }
        CP_COMMIT();
    }

    float4 xv[4];
#pragma unroll
    for (int it = 0; it < 4; it++) {
        int idx = tid + it * 256;
        int r = idx >> 4, c4 = idx & 15;
        xv[it] = x4[(size_t)(row0 + r) * 128 + c4];
    }

    for (int ch = 0; ch < 8; ch++) {
        // convert x regs -> A fp16 smem
#pragma unroll
        for (int it = 0; it < 4; it++) {
            int idx = tid + it * 256;
            int r = idx >> 4, c4 = idx & 15;
            float4 v = xv[it];
            uint32_t off = (uint32_t)r * RS2 + (uint32_t)c4 * 8;
            *(uint2*)(sm + QK_A + off) =
                make_uint2(pack_h2(v.x, v.y), pack_h2(v.z, v.w));
        }

        // prefetch chunk ch+1
        if (ch < 7) {
            const int c1 = (ch + 1) * 64;
#pragma unroll
            for (int it = 0; it < 4; it++) {
                int idx = tid + it * 256;
                int r = idx >> 4, c4 = idx & 15;
                xv[it] = x4[(size_t)(row0 + r) * 128 + (c1 >> 2) + c4];
            }
            const uint32_t bb = ((ch + 1) & 1) ? QK_B1 : QK_B0;
#pragma unroll
            for (int it = 0; it < 6; it++) {
                int idx = tid + it * 256;
                int n = idx >> 3, part = idx & 7;
                size_t gs = ((size_t)n * C_ + c1) * 2 + (size_t)part * 16;
                uint32_t off = (uint32_t)n * RS2 + (uint32_t)part * 16;
                cp_async16(smb + bb + off, (const char*)g_w16 + gs);
            }
            CP_COMMIT();
            CP_WAIT(1);
        } else {
            CP_WAIT(0);
        }
        __syncthreads();

        const uint32_t bbuf = (ch & 1) ? QK_B1 : QK_B0;
#pragma unroll
        for (int ks = 0; ks < 4; ks++) {
            uint32_t a[2][4];
#pragma unroll
            for (int mt = 0; mt < 2; mt++) {
                uint32_t off = a_row_off + (uint32_t)mt * 16 * RS2 + (uint32_t)ks * 32;
                ldsm_x4(a[mt][0], a[mt][1], a[mt][2], a[mt][3], smb + QK_A + off);
            }
            uint32_t bfr[6][2];
#pragma unroll
            for (int np = 0; np < 3; np++) {
                uint32_t off = b_row_off + (uint32_t)np * 16 * RS2 + (uint32_t)ks * 32;
                ldsm_x4(bfr[np*2][0], bfr[np*2][1], bfr[np*2+1][0], bfr[np*2+1][1],
                        smb + bbuf + off);
            }
#pragma unroll
            for (int mt = 0; mt < 2; mt++)
#pragma unroll
                for (int nt = 0; nt < 6; nt++)
                    mma_f16(c[mt][nt], a[mt], bfr[nt]);
        }
        __syncthreads();
    }

    // epilogue: fp16 writes; q pre-scaled by C^-0.5
    const float SCALE = 0.04419417382415922f;
    const int g  = lane >> 2;
    const int tg = lane & 3;
#pragma unroll
    for (int nt = 0; nt < 6; nt++) {
        int col0 = n0 + nt * 8;
        int w = col0 >> 6;
        int h = (col0 & 63) + tg * 2;
        float mul = (w == 0) ? SCALE : 1.0f;
        __half* op = (w == 0) ? g_q16 : (w == 1) ? g_k16 : g_v16;
#pragma unroll
        for (int mt = 0; mt < 2; mt++)
#pragma unroll
            for (int rr = 0; rr < 2; rr++) {
                int row = row0 + m0 + mt * 16 + g + rr * 8;
                size_t o = (size_t)row * H_ + h;
                *(uint32_t*)(op + o) = pack_h2(c[mt][nt][rr * 2 + 0] * mul,
                                               c[mt][nt][rr * 2 + 1] * mul);
            }
    }
}

// ---------------------------------------------------------------------------
// Kernel 2: fp16 tensor-core causal flash attention, Q-tile 128,
// cp.async double-buffered K/V stages, per-warp causal skip.
// 256 threads = 8 warps, warp = 16 q rows.
// smem: Q 0 (18432), stage0 @18432 (K 9216, V 9216), stage1 @36864.
// total 55296 B.
// ---------------------------------------------------------------------------
#define AT_Q  0
#define AT_ST0 18432
#define AT_STAGE 18432
#define AT_K 0
#define AT_V 9216
#define A_SMEM 55296

__global__ __launch_bounds__(256, 2) void attn_mma(float* __restrict__ out)
{
    extern __shared__ char sm[];
    const uint32_t smb = smem_u32(sm);

    const int b    = blockIdx.x;
    const int qt   = 1 - blockIdx.y;           // heavy tile first
    const int tid  = threadIdx.x;
    const int w    = tid >> 5;
    const int lane = tid & 31;
    const int g    = lane >> 2;
    const int tg   = lane & 3;

    const int rowbase = qt * 128 + w * 16;
    const int nkt = qt * 2 + 2;

    // Q tile (128 rows) + prologue K/V stage 0
    {
        const size_t base = ((size_t)b * T_ + qt * 128) * H_;   // halves
        for (int idx = tid; idx < 1024; idx += 256) {
            int r = idx >> 3, part = idx & 7;
            size_t gs = (base + (size_t)r * H_ + part * 8) * 2;
            uint32_t off = (uint32_t)r * RS2 + part * 16;
            *(uint4*)(sm + AT_Q + off) = *(const uint4*)((const char*)g_q16 + gs);
        }
        const size_t kbase = ((size_t)b * T_) * H_;
        const uint32_t stg = smb + AT_ST0;
        for (int idx = tid; idx < 512; idx += 256) {
            int r = idx >> 3, part = idx & 7;
            size_t gs = (kbase + (size_t)r * H_ + part * 8) * 2;
            uint32_t off = (uint32_t)r * RS2 + part * 16;
            cp_async16(stg + AT_K + off, (const char*)g_k16 + gs);
            cp_async16(stg + AT_V + off, (const char*)g_v16 + gs);
        }
        CP_COMMIT();
    }
    __syncthreads();

    // preload Q A-frags
    uint32_t qa[4][4];
    {
        uint32_t a_row_off = (uint32_t)(w * 16 + (lane & 15)) * RS2
                           + (uint32_t)(lane >> 4) * 16;
#pragma unroll
        for (int ks = 0; ks < 4; ks++)
            ldsm_x4(qa[ks][0], qa[ks][1], qa[ks][2], qa[ks][3],
                    smb + AT_Q + a_row_off + ks * 32);
    }

    float o[8][4];
#pragma unroll
    for (int nt = 0; nt < 8; nt++)
#pragma unroll
        for (int i = 0; i < 4; i++) o[nt][i] = 0.f;
    float m0r = -INFINITY, m1r = -INFINITY;
    float l0r = 0.f, l1r = 0.f;

    const uint32_t kb_off = (uint32_t)(((lane >> 4) & 1) * 8 + (lane & 7)) * RS2
                          + (uint32_t)((lane >> 3) & 1) * 16;
    const uint32_t vb_off = (uint32_t)(((lane >> 3) & 1) * 8 + (lane & 7)) * RS2
                          + (uint32_t)((lane >> 4) & 1) * 16;

    for (int kt = 0; kt < nkt; kt++) {
        if (kt + 1 < nkt) {
            const size_t kbase = ((size_t)b * T_ + (kt + 1) * 64) * H_;
            const uint32_t stg = smb + AT_ST0 + ((kt + 1) & 1) * AT_STAGE;
            for (int idx = tid; idx < 512; idx += 256) {
                int r = idx >> 3, part = idx & 7;
                size_t gs = (kbase + (size_t)r * H_ + part * 8) * 2;
                uint32_t off = (uint32_t)r * RS2 + part * 16;
                cp_async16(stg + AT_K + off, (const char*)g_k16 + gs);
                cp_async16(stg + AT_V + off, (const char*)g_v16 + gs);
            }
            CP_COMMIT();
            CP_WAIT(1);
        } else {
            CP_WAIT(0);
        }
        __syncthreads();

        const int kcol0 = kt * 64;
        if (kcol0 <= rowbase + 15) {
            const uint32_t stg = smb + AT_ST0 + (kt & 1) * AT_STAGE;

            // S = Q K^T
            float s[8][4];
#pragma unroll
            for (int nt = 0; nt < 8; nt++)
#pragma unroll
                for (int i = 0; i < 4; i++) s[nt][i] = 0.f;

#pragma unroll
            for (int ks = 0; ks < 4; ks++) {
                uint32_t bfr[8][2];
#pragma unroll
                for (int np = 0; np < 4; np++) {
                    uint32_t off = kb_off + (uint32_t)np * 16 * RS2 + (uint32_t)ks * 32;
                    ldsm_x4(bfr[np*2][0], bfr[np*2][1], bfr[np*2+1][0], bfr[np*2+1][1],
                            stg + AT_K + off);
                }
#pragma unroll
                for (int nt = 0; nt < 8; nt++)
                    mma_f16(s[nt], qa[ks], bfr[nt]);
            }

            // causal mask (diagonal region)
            if (kcol0 + 63 > rowbase) {
                const int r0g = rowbase + g;
#pragma unroll
                for (int nt = 0; nt < 8; nt++) {
                    int cg = kcol0 + nt * 8 + tg * 2;
                    if (cg > r0g)         s[nt][0] = -1e30f;
                    if (cg + 1 > r0g)     s[nt][1] = -1e30f;
                    if (cg > r0g + 8)     s[nt][2] = -1e30f;
                    if (cg + 1 > r0g + 8) s[nt][3] = -1e30f;
                }
            }

            // online softmax
            float mt0 = -INFINITY, mt1 = -INFINITY;
#pragma unroll
            for (int nt = 0; nt < 8; nt++) {
                mt0 = fmaxf(mt0, fmaxf(s[nt][0], s[nt][1]));
                mt1 = fmaxf(mt1, fmaxf(s[nt][2], s[nt][3]));
            }
            mt0 = fmaxf(mt0, __shfl_xor_sync(0xffffffff, mt0, 1));
            mt0 = fmaxf(mt0, __shfl_xor_sync(0xffffffff, mt0, 2));
            mt1 = fmaxf(mt1, __shfl_xor_sync(0xffffffff, mt1, 1));
            mt1 = fmaxf(mt1, __shfl_xor_sync(0xffffffff, mt1, 2));

            float mn0 = fmaxf(m0r, mt0);
            float mn1 = fmaxf(m1r, mt1);
            float cr0 = __expf(m0r - mn0);
            float cr1 = __expf(m1r - mn1);
            m0r = mn0; m1r = mn1;

            float ls0 = 0.f, ls1 = 0.f;
#pragma unroll
            for (int nt = 0; nt < 8; nt++) {
                s[nt][0] = __expf(s[nt][0] - mn0);
                s[nt][1] = __expf(s[nt][1] - mn0);
                s[nt][2] = __expf(s[nt][2] - mn1);
                s[nt][3] = __expf(s[nt][3] - mn1);
                ls0 += s[nt][0] + s[nt][1];
                ls1 += s[nt][2] + s[nt][3];
            }
            l0r = l0r * cr0 + ls0;
            l1r = l1r * cr1 + ls1;

#pragma unroll
            for (int nt = 0; nt < 8; nt++) {
                o[nt][0] *= cr0; o[nt][1] *= cr0;
                o[nt][2] *= cr1; o[nt][3] *= cr1;
            }

            // repack P -> fp16 A-frags
            uint32_t pa[4][4];
#pragma unroll
            for (int j = 0; j < 4; j++) {
                pa[j][0] = pack_h2(s[2*j][0],   s[2*j][1]);
                pa[j][1] = pack_h2(s[2*j][2],   s[2*j][3]);
                pa[j][2] = pack_h2(s[2*j+1][0], s[2*j+1][1]);
                pa[j][3] = pack_h2(s[2*j+1][2], s[2*j+1][3]);
            }

            // O += P V
#pragma unroll
            for (int ks = 0; ks < 4; ks++) {
                uint32_t vb[8][2];
#pragma unroll
                for (int nt2 = 0; nt2 < 4; nt2++) {
                    uint32_t off = vb_off + (uint32_t)(ks * 16) * RS2 + (uint32_t)nt2 * 32;
                    ldsm_x4_t(vb[nt2*2][0], vb[nt2*2][1], vb[nt2*2+1][0], vb[nt2*2+1][1],
                              stg + AT_V + off);
                }
#pragma unroll
                for (int nt = 0; nt < 8; nt++)
                    mma_f16(o[nt], pa[ks], vb[nt]);
            }
        }
        __syncthreads();
    }

    // finalize
    l0r += __shfl_xor_sync(0xffffffff, l0r, 1);
    l0r += __shfl_xor_sync(0xffffffff, l0r, 2);
    l1r += __shfl_xor_sync(0xffffffff, l1r, 1);
    l1r += __shfl_xor_sync(0xffffffff, l1r, 2);
    float inv0 = 1.f / l0r;
    float inv1 = 1.f / l1r;

    const int q0 = rowbase + g;
#pragma unroll
    for (int nt = 0; nt < 8; nt++) {
        int h = nt * 8 + tg * 2;
        *(float2*)&out[((size_t)b * T_ + q0) * H_ + h] =
            make_float2(o[nt][0] * inv0, o[nt][1] * inv0);
        *(float2*)&out[((size_t)b * T_ + q0 + 8) * H_ + h] =
            make_float2(o[nt][2] * inv1, o[nt][3] * inv1);
    }
}

// ---------------------------------------------------------------------------
extern "C" void kernel_launch(void* const* d_in, const int* in_sizes, int n_in,
                              void* d_out, int out_size)
{
    const float* x  = (const float*)d_in[0];
    const float* Wk = (const float*)d_in[1];
    const float* Wq = (const float*)d_in[2];
    const float* Wv = (const float*)d_in[3];
    float* out = (float*)d_out;

    cudaFuncSetAttribute(qkv_gemm_pipe,
                         cudaFuncAttributeMaxDynamicSharedMemorySize, QK_SMEM);
    cudaFuncSetAttribute(attn_mma,
                         cudaFuncAttributeMaxDynamicSharedMemorySize, A_SMEM);

    wconv<<<(3 * H_ * C_ + 255) / 256, 256>>>(Wq, Wk, Wv);
    qkv_gemm_pipe<<<BT_ / 64, 256, QK_SMEM>>>(x);

    dim3 g2(B_, T_ / 128);
    attn_mma<<<g2, 256, A_SMEM>>>(out);
}